// round 7
// baseline (speedup 1.0000x reference)
#include <cuda_runtime.h>
#include <cuda_bf16.h>
#include <math.h>
#include <stdint.h>

// B=2, S=2048, D_MODEL=1024, HEADS=16, D_K=64, D_FF=4096, tokens M=4096

// ---------------------------------------------------------------- scratch
__device__ __align__(128) float g_q [1u<<22];
__device__ __align__(128) float g_k [1u<<22];
__device__ __align__(128) float g_v [1u<<22];
__device__ __align__(128) float g_y [1u<<22];
__device__ __align__(128) float g_x [1u<<22];
__device__ __align__(128) float g_y2[1u<<22];
__device__ __align__(128) __nv_bfloat16 g_qkin_h[1u<<22], g_qkin_l[1u<<22];
__device__ __align__(128) __nv_bfloat16 g_src_h [1u<<22], g_src_l [1u<<22];
__device__ __align__(128) __nv_bfloat16 g_ctx_h [1u<<22], g_ctx_l [1u<<22];
__device__ __align__(128) __nv_bfloat16 g_x_h   [1u<<22], g_x_l   [1u<<22];
__device__ __align__(128) __nv_bfloat16 g_ff_h  [1u<<24], g_ff_l  [1u<<24];
__device__ __align__(128) __nv_bfloat16 g_wt_h  [12u<<20], g_wt_l [12u<<20];

// ---------------------------------------------------------------- helpers
__device__ __forceinline__ uint32_t smem_u32(const void* p) {
    uint32_t a;
    asm("{ .reg .u64 t; cvta.to.shared.u64 t, %1; cvt.u32.u64 %0, t; }" : "=r"(a) : "l"(p));
    return a;
}
__device__ __forceinline__ void cp16(uint32_t dst, const void* src) {
    asm volatile("cp.async.cg.shared.global [%0], [%1], 16;"
                 :: "r"(dst), "l"(__cvta_generic_to_global(src)) : "memory");
}
#define CP_COMMIT() asm volatile("cp.async.commit_group;" ::: "memory")
#define CP_WAIT1()  asm volatile("cp.async.wait_group 1;"  ::: "memory")

#define LDSM4(r, addr) \
    asm volatile("ldmatrix.sync.aligned.m8n8.x4.shared.b16 {%0,%1,%2,%3}, [%4];" \
                 : "=r"((r)[0]), "=r"((r)[1]), "=r"((r)[2]), "=r"((r)[3]) : "r"(addr))

#define MMA16816(d, a, b) \
    asm volatile("mma.sync.aligned.m16n8k16.row.col.f32.bf16.bf16.f32 " \
                 "{%0,%1,%2,%3}, {%4,%5,%6,%7}, {%8,%9}, {%0,%1,%2,%3};" \
                 : "+f"((d)[0]), "+f"((d)[1]), "+f"((d)[2]), "+f"((d)[3]) \
                 : "r"((a)[0]), "r"((a)[1]), "r"((a)[2]), "r"((a)[3]), \
                   "r"((b)[0]), "r"((b)[1]))

__device__ __forceinline__ void split_store4(__nv_bfloat16* __restrict__ H,
                                             __nv_bfloat16* __restrict__ L, float4 v) {
    union { __nv_bfloat16 b[4]; uint2 u; } hv, lv;
    hv.b[0] = __float2bfloat16(v.x); lv.b[0] = __float2bfloat16(v.x - __bfloat162float(hv.b[0]));
    hv.b[1] = __float2bfloat16(v.y); lv.b[1] = __float2bfloat16(v.y - __bfloat162float(hv.b[1]));
    hv.b[2] = __float2bfloat16(v.z); lv.b[2] = __float2bfloat16(v.z - __bfloat162float(hv.b[2]));
    hv.b[3] = __float2bfloat16(v.w); lv.b[3] = __float2bfloat16(v.w - __bfloat162float(hv.b[3]));
    *(uint2*)H = hv.u;
    *(uint2*)L = lv.u;
}
__device__ __forceinline__ void split_store2(__nv_bfloat16* __restrict__ H,
                                             __nv_bfloat16* __restrict__ L,
                                             float x, float y) {
    union { __nv_bfloat16 b[2]; uint32_t u; } hv, lv;
    hv.b[0] = __float2bfloat16(x); lv.b[0] = __float2bfloat16(x - __bfloat162float(hv.b[0]));
    hv.b[1] = __float2bfloat16(y); lv.b[1] = __float2bfloat16(y - __bfloat162float(hv.b[1]));
    *(uint32_t*)H = hv.u;
    *(uint32_t*)L = lv.u;
}

// ================================================================ HMMA GEMM
// C[M,N] = act( A @ B^T + bias (+R) )
// A = Ah+Al [M,K] bf16 K-major; B = Bh+Bl [N,K] bf16 K-major.
// CTA 128x128, 256 threads (8 warps = 4m x 2n, warp tile 32x64),
// K chunks of 32, 3-stage cp.async pipeline, padded smem (80B rows).
#define ST      3
#define CHUNK   32
#define ROWB    80                 // bytes per smem row (40 bf16)
#define MATB    (128 * ROWB)       // 10240
#define STAGEB  (4 * MATB)         // 40960
#define GEMM_SMEM (ST * STAGEB)    // 122880

template<bool RELU, bool RESID, bool SPLIT>
__global__ __launch_bounds__(256, 1)
void gemm_tc(const __nv_bfloat16* __restrict__ Ah, const __nv_bfloat16* __restrict__ Al,
             const __nv_bfloat16* __restrict__ Bh, const __nv_bfloat16* __restrict__ Bl,
             const float* __restrict__ bias, const float* __restrict__ Rsd,
             float* __restrict__ Cf, __nv_bfloat16* __restrict__ Ch, __nv_bfloat16* __restrict__ Cl,
             int M, int N, int K)
{
    extern __shared__ __align__(128) char smem[];
    const uint32_t sb = smem_u32(smem);
    const int tid  = threadIdx.x;
    const int wid  = tid >> 5, lane = tid & 31;
    const int bm   = blockIdx.y * 128, bn = blockIdx.x * 128;
    const int m0   = (wid & 3) * 32;         // warp row offset in tile
    const int n0   = (wid >> 2) * 64;        // warp col offset in tile
    const int nt   = K / CHUNK;

    float acc[2][8][4];
    #pragma unroll
    for (int i = 0; i < 2; i++)
        #pragma unroll
        for (int j = 0; j < 8; j++)
            #pragma unroll
            for (int q = 0; q < 4; q++) acc[i][j][q] = 0.f;

    auto stage = [&](int c) {
        const uint32_t base = sb + (uint32_t)(c % ST) * STAGEB;
        const size_t kof = (size_t)c * CHUNK;
        #pragma unroll
        for (int i = 0; i < 2; i++) {
            const int f   = tid + i * 256;      // 0..511
            const int row = f >> 2, ch = f & 3;
            const uint32_t so = row * ROWB + ch * 16;
            const size_t ga = (size_t)(bm + row) * K + kof + ch * 8;
            const size_t gb = (size_t)(bn + row) * K + kof + ch * 8;
            cp16(base +            so, Ah + ga);
            cp16(base +     MATB + so, Al + ga);
            cp16(base + 2 * MATB + so, Bh + gb);
            cp16(base + 3 * MATB + so, Bl + gb);
        }
        CP_COMMIT();
    };

    stage(0);
    stage(1);

    // per-lane ldmatrix address components
    const uint32_t a_row  = m0 + (lane & 15);
    const uint32_t a_coff = (uint32_t)((lane >> 4) << 4);              // bytes
    const uint32_t b_row  = n0 + ((lane >> 4) << 3) + (lane & 7);
    const uint32_t b_coff = (uint32_t)(((lane >> 3) & 1) << 4);        // bytes

    for (int c = 0; c < nt; c++) {
        if (c + ST - 1 < nt) stage(c + ST - 1);
        else                 CP_COMMIT();
        CP_WAIT1();
        __syncthreads();

        const uint32_t base = sb + (uint32_t)(c % ST) * STAGEB;
        #pragma unroll
        for (int ks = 0; ks < 2; ks++) {
            uint32_t aH[2][4], aL[2][4], bH[8][2], bL[8][2];
            #pragma unroll
            for (int mi = 0; mi < 2; mi++) {
                const uint32_t ra = base + (a_row + mi * 16) * ROWB + ks * 32 + a_coff;
                LDSM4(aH[mi], ra);
                LDSM4(aL[mi], ra + MATB);
            }
            #pragma unroll
            for (int t = 0; t < 4; t++) {
                const uint32_t rb = base + 2 * MATB + (b_row + t * 16) * ROWB + ks * 32 + b_coff;
                uint32_t r[4];
                LDSM4(r, rb);
                bH[2*t][0] = r[0]; bH[2*t][1] = r[1];
                bH[2*t+1][0] = r[2]; bH[2*t+1][1] = r[3];
                LDSM4(r, rb + MATB);
                bL[2*t][0] = r[0]; bL[2*t][1] = r[1];
                bL[2*t+1][0] = r[2]; bL[2*t+1][1] = r[3];
            }
            #pragma unroll
            for (int mi = 0; mi < 2; mi++)
                #pragma unroll
                for (int ni = 0; ni < 8; ni++) {
                    MMA16816(acc[mi][ni], aH[mi], bH[ni]);
                    MMA16816(acc[mi][ni], aL[mi], bH[ni]);
                    MMA16816(acc[mi][ni], aH[mi], bL[ni]);
                }
        }
        __syncthreads();
    }

    // epilogue: fragment -> global
    #pragma unroll
    for (int mi = 0; mi < 2; mi++) {
        #pragma unroll
        for (int half = 0; half < 2; half++) {
            const int r = bm + m0 + mi * 16 + half * 8 + (lane >> 2);
            const size_t orow = (size_t)r * N;
            #pragma unroll
            for (int ni = 0; ni < 8; ni++) {
                const int cc = bn + n0 + ni * 8 + (lane & 3) * 2;
                float vx = acc[mi][ni][half * 2 + 0];
                float vy = acc[mi][ni][half * 2 + 1];
                const float2 b2 = *(const float2*)(bias + cc);
                vx += b2.x; vy += b2.y;
                if constexpr (RESID) {
                    const float2 rr = *(const float2*)(Rsd + orow + cc);
                    vx += rr.x; vy += rr.y;
                }
                if constexpr (RELU) { vx = fmaxf(vx, 0.f); vy = fmaxf(vy, 0.f); }
                if constexpr (SPLIT) split_store2(Ch + orow + cc, Cl + orow + cc, vx, vy);
                else { float2 o; o.x = vx; o.y = vy; *(float2*)(Cf + orow + cc) = o; }
            }
        }
    }
}

// ================================================================ weight transpose+split
// W[K,N] fp32 -> Th,Tl[N,K] bf16
__global__ __launch_bounds__(256)
void tsplit_kernel(const float* __restrict__ W, __nv_bfloat16* __restrict__ Th,
                   __nv_bfloat16* __restrict__ Tl, int K, int N)
{
    __shared__ float t[32][33];
    const int n0 = blockIdx.x * 32, k0 = blockIdx.y * 32;
    const int tx = threadIdx.x, ty = threadIdx.y;
    #pragma unroll
    for (int i = 0; i < 32; i += 8)
        t[ty + i][tx] = W[(size_t)(k0 + ty + i) * N + n0 + tx];
    __syncthreads();
    #pragma unroll
    for (int i = 0; i < 32; i += 8) {
        const float v = t[tx][ty + i];
        const __nv_bfloat16 h = __float2bfloat16(v);
        const __nv_bfloat16 l = __float2bfloat16(v - __bfloat162float(h));
        const size_t o = (size_t)(n0 + ty + i) * K + k0 + tx;
        Th[o] = h; Tl[o] = l;
    }
}

// activation split (optionally a+b first)
template<bool ADD>
__global__ __launch_bounds__(256)
void split_kernel(const float* __restrict__ a, const float* __restrict__ b,
                  __nv_bfloat16* __restrict__ H, __nv_bfloat16* __restrict__ L)
{
    const size_t i = ((size_t)blockIdx.x * 256 + threadIdx.x) * 4;
    float4 v = *(const float4*)(a + i);
    if constexpr (ADD) {
        const float4 w = *(const float4*)(b + i);
        v.x += w.x; v.y += w.y; v.z += w.z; v.w += w.w;
    }
    split_store4(H + i, L + i, v);
}

// ================================================================ flash attention (fp32 SIMT)
__global__ __launch_bounds__(128, 2)
void attn_kernel(const float* __restrict__ Q, const float* __restrict__ Kp,
                 const float* __restrict__ V, const float* __restrict__ corr,
                 __nv_bfloat16* __restrict__ ctx_h, __nv_bfloat16* __restrict__ ctx_l)
{
    __shared__ float Ks[32][64];
    __shared__ float Vs[32][64];
    __shared__ float Cs[128][33];

    const int tid = threadIdx.x;
    const int q0  = blockIdx.x * 128;
    const int b   = blockIdx.y >> 4;
    const int h   = blockIdx.y & 15;

    const size_t qbase = ((size_t)(b * 2048 + q0 + tid)) * 1024 + h * 64;
    float Qr[64];
    #pragma unroll
    for (int i = 0; i < 16; i++) {
        const float4 t = *(const float4*)(Q + qbase + i * 4);
        Qr[i*4+0] = t.x * 0.125f;  Qr[i*4+1] = t.y * 0.125f;
        Qr[i*4+2] = t.z * 0.125f;  Qr[i*4+3] = t.w * 0.125f;
    }
    float Or[64];
    #pragma unroll
    for (int d = 0; d < 64; d++) Or[d] = 0.f;
    float m = -1e30f, l = 0.f;

    const size_t kvbase = (size_t)b * 2048 * 1024 + h * 64;
    const size_t cbase  = ((size_t)b * 2048 + q0) * 2048;

    for (int k0 = 0; k0 < 2048; k0 += 32) {
        #pragma unroll
        for (int i = 0; i < 4; i++) {
            const int f = tid + i * 128;
            const int row = f >> 4;
            const int c4  = (f & 15) << 2;
            const size_t g = kvbase + (size_t)(k0 + row) * 1024 + c4;
            *(float4*)&Ks[row][c4] = *(const float4*)(Kp + g);
            *(float4*)&Vs[row][c4] = *(const float4*)(V + g);
        }
        #pragma unroll
        for (int i = 0; i < 8; i++) {
            const int f = tid + i * 128;
            const int row = f >> 3;
            const int c4  = (f & 7) << 2;
            const float4 cv = *(const float4*)(corr + cbase + (size_t)row * 2048 + k0 + c4);
            Cs[row][c4+0] = cv.x; Cs[row][c4+1] = cv.y;
            Cs[row][c4+2] = cv.z; Cs[row][c4+3] = cv.w;
        }
        __syncthreads();

        #pragma unroll 2
        for (int j = 0; j < 32; j++) {
            const float4* kr = (const float4*)Ks[j];
            float s0 = Cs[tid][j], s1 = 0.f, s2 = 0.f, s3 = 0.f;
            #pragma unroll
            for (int d4 = 0; d4 < 16; d4++) {
                const float4 kv = kr[d4];
                s0 += Qr[d4*4+0] * kv.x;
                s1 += Qr[d4*4+1] * kv.y;
                s2 += Qr[d4*4+2] * kv.z;
                s3 += Qr[d4*4+3] * kv.w;
            }
            const float s = (s0 + s1) + (s2 + s3);
            float p;
            if (s > m) {
                const float sc = __expf(m - s);
                l *= sc;
                #pragma unroll
                for (int d = 0; d < 64; d++) Or[d] *= sc;
                m = s;
                p = 1.f;
            } else {
                p = __expf(s - m);
            }
            l += p;
            const float4* vr = (const float4*)Vs[j];
            #pragma unroll
            for (int d4 = 0; d4 < 16; d4++) {
                const float4 vv = vr[d4];
                Or[d4*4+0] += p * vv.x;
                Or[d4*4+1] += p * vv.y;
                Or[d4*4+2] += p * vv.z;
                Or[d4*4+3] += p * vv.w;
            }
        }
        __syncthreads();
    }

    const float inv = 1.f / l;
    #pragma unroll
    for (int i = 0; i < 16; i++) {
        float4 o;
        o.x = Or[i*4+0] * inv;  o.y = Or[i*4+1] * inv;
        o.z = Or[i*4+2] * inv;  o.w = Or[i*4+3] * inv;
        split_store4(ctx_h + qbase + i * 4, ctx_l + qbase + i * 4, o);
    }
}

// ================================================================ LayerNorm (optional bf16 split out)
template<bool SPLIT>
__global__ __launch_bounds__(256)
void ln_kernel(const float* __restrict__ in, const float* __restrict__ g,
               const float* __restrict__ b, float* __restrict__ out,
               __nv_bfloat16* __restrict__ H, __nv_bfloat16* __restrict__ L)
{
    __shared__ float rs[8], rq[8];
    const int tid = threadIdx.x;
    const size_t base = (size_t)blockIdx.x * 1024;

    const float4 v = *(const float4*)(in + base + tid * 4);
    float s  = v.x + v.y + v.z + v.w;
    float q2 = v.x*v.x + v.y*v.y + v.z*v.z + v.w*v.w;
    #pragma unroll
    for (int o = 16; o > 0; o >>= 1) {
        s  += __shfl_xor_sync(0xffffffffu, s,  o);
        q2 += __shfl_xor_sync(0xffffffffu, q2, o);
    }
    if ((tid & 31) == 0) { rs[tid >> 5] = s; rq[tid >> 5] = q2; }
    __syncthreads();
    float ts = 0.f, tq = 0.f;
    #pragma unroll
    for (int w = 0; w < 8; w++) { ts += rs[w]; tq += rq[w]; }

    const float mu   = ts * (1.f / 1024.f);
    const float var  = tq * (1.f / 1024.f) - mu * mu;
    const float invs = rsqrtf(var + 1e-5f);

    const float4 gg = *(const float4*)(g + tid * 4);
    const float4 bb = *(const float4*)(b + tid * 4);
    float4 o;
    o.x = (v.x - mu) * invs * gg.x + bb.x;
    o.y = (v.y - mu) * invs * gg.y + bb.y;
    o.z = (v.z - mu) * invs * gg.z + bb.z;
    o.w = (v.w - mu) * invs * gg.w + bb.w;
    *(float4*)(out + base + tid * 4) = o;
    if constexpr (SPLIT) split_store4(H + base + tid * 4, L + base + tid * 4, o);
}

// ================================================================ launch
extern "C" void kernel_launch(void* const* d_in, const int* in_sizes, int n_in,
                              void* d_out, int out_size)
{
    (void)in_sizes; (void)n_in; (void)out_size;
    const float* src  = (const float*)d_in[0];
    const float* corr = (const float*)d_in[1];
    const float* pos  = (const float*)d_in[2];
    const float* Wq   = (const float*)d_in[3];
    const float* bq   = (const float*)d_in[4];
    const float* Wk   = (const float*)d_in[5];
    const float* bk   = (const float*)d_in[6];
    const float* Wv   = (const float*)d_in[7];
    const float* bv   = (const float*)d_in[8];
    const float* Wo   = (const float*)d_in[9];
    const float* bo   = (const float*)d_in[10];
    const float* W1   = (const float*)d_in[11];
    const float* b1   = (const float*)d_in[12];
    const float* W2   = (const float*)d_in[13];
    const float* b2   = (const float*)d_in[14];
    const float* g1   = (const float*)d_in[15];
    const float* be1  = (const float*)d_in[16];
    const float* g2   = (const float*)d_in[17];
    const float* be2  = (const float*)d_in[18];
    float* out = (float*)d_out;

    float *q, *k, *v, *y, *x, *y2;
    __nv_bfloat16 *qkh, *qkl, *sh, *sl, *cth, *ctl, *xh, *xl, *ffh, *ffl, *wth, *wtl;
    cudaGetSymbolAddress((void**)&q,   g_q);    cudaGetSymbolAddress((void**)&k,   g_k);
    cudaGetSymbolAddress((void**)&v,   g_v);    cudaGetSymbolAddress((void**)&y,   g_y);
    cudaGetSymbolAddress((void**)&x,   g_x);    cudaGetSymbolAddress((void**)&y2,  g_y2);
    cudaGetSymbolAddress((void**)&qkh, g_qkin_h); cudaGetSymbolAddress((void**)&qkl, g_qkin_l);
    cudaGetSymbolAddress((void**)&sh,  g_src_h);  cudaGetSymbolAddress((void**)&sl,  g_src_l);
    cudaGetSymbolAddress((void**)&cth, g_ctx_h);  cudaGetSymbolAddress((void**)&ctl, g_ctx_l);
    cudaGetSymbolAddress((void**)&xh,  g_x_h);    cudaGetSymbolAddress((void**)&xl,  g_x_l);
    cudaGetSymbolAddress((void**)&ffh, g_ff_h);   cudaGetSymbolAddress((void**)&ffl, g_ff_l);
    cudaGetSymbolAddress((void**)&wth, g_wt_h);   cudaGetSymbolAddress((void**)&wtl, g_wt_l);

    // packed transposed-weight offsets (elements)
    const size_t OQ = 0, OK_ = 1u<<20, OV = 2u<<20, OO = 3u<<20, O1 = 4u<<20, O2 = 8u<<20;

    cudaFuncSetAttribute(gemm_tc<false,false,false>, cudaFuncAttributeMaxDynamicSharedMemorySize, GEMM_SMEM);
    cudaFuncSetAttribute(gemm_tc<false,true ,false>, cudaFuncAttributeMaxDynamicSharedMemorySize, GEMM_SMEM);
    cudaFuncSetAttribute(gemm_tc<true ,false,true >, cudaFuncAttributeMaxDynamicSharedMemorySize, GEMM_SMEM);

    const dim3 tb(32, 8);
    // weight transpose+split
    tsplit_kernel<<<dim3(1024/32, 1024/32), tb>>>(Wq, wth + OQ,  wtl + OQ,  1024, 1024);
    tsplit_kernel<<<dim3(1024/32, 1024/32), tb>>>(Wk, wth + OK_, wtl + OK_, 1024, 1024);
    tsplit_kernel<<<dim3(1024/32, 1024/32), tb>>>(Wv, wth + OV,  wtl + OV,  1024, 1024);
    tsplit_kernel<<<dim3(1024/32, 1024/32), tb>>>(Wo, wth + OO,  wtl + OO,  1024, 1024);
    tsplit_kernel<<<dim3(4096/32, 1024/32), tb>>>(W1, wth + O1,  wtl + O1,  1024, 4096);
    tsplit_kernel<<<dim3(1024/32, 4096/32), tb>>>(W2, wth + O2,  wtl + O2,  4096, 1024);

    // activation splits
    split_kernel<true ><<<4096, 256>>>(src, pos,     qkh, qkl);   // q/k input = src + pos
    split_kernel<false><<<4096, 256>>>(src, nullptr, sh,  sl);    // v input = src

    const dim3 gP(8, 32), gF1(32, 32);
    // projections
    gemm_tc<false,false,false><<<gP, 256, GEMM_SMEM>>>(qkh, qkl, wth + OQ,  wtl + OQ,  bq, nullptr, q,  nullptr, nullptr, 4096, 1024, 1024);
    gemm_tc<false,false,false><<<gP, 256, GEMM_SMEM>>>(qkh, qkl, wth + OK_, wtl + OK_, bk, nullptr, k,  nullptr, nullptr, 4096, 1024, 1024);
    gemm_tc<false,false,false><<<gP, 256, GEMM_SMEM>>>(sh,  sl,  wth + OV,  wtl + OV,  bv, nullptr, v,  nullptr, nullptr, 4096, 1024, 1024);

    attn_kernel<<<dim3(2048/128, 32), 128>>>(q, k, v, corr, cth, ctl);

    // output projection + residual(src) -> y ; LN1 -> x (+ bf16 split)
    gemm_tc<false,true ,false><<<gP, 256, GEMM_SMEM>>>(cth, ctl, wth + OO, wtl + OO, bo, src, y, nullptr, nullptr, 4096, 1024, 1024);
    ln_kernel<true ><<<4096, 256>>>(y, g1, be1, x, xh, xl);

    // FFN1: relu -> bf16 split directly ; FFN2 + residual(x) -> y2 ; LN2 -> out
    gemm_tc<true ,false,true ><<<gF1, 256, GEMM_SMEM>>>(xh,  xl,  wth + O1, wtl + O1, b1, nullptr, nullptr, ffh, ffl, 4096, 4096, 1024);
    gemm_tc<false,true ,false><<<gP,  256, GEMM_SMEM>>>(ffh, ffl, wth + O2, wtl + O2, b2, x,       y2, nullptr, nullptr, 4096, 1024, 4096);
    ln_kernel<false><<<4096, 256>>>(y2, g2, be2, out, nullptr, nullptr);
}

// round 8
// speedup vs baseline: 1.0008x; 1.0008x over previous
#include <cuda_runtime.h>
#include <cuda_bf16.h>
#include <math.h>
#include <stdint.h>

// B=2, S=2048, D_MODEL=1024, HEADS=16, D_K=64, D_FF=4096, tokens M=4096

// ---------------------------------------------------------------- scratch
__device__ __align__(128) float g_q [1u<<22];
__device__ __align__(128) float g_k [1u<<22];
__device__ __align__(128) float g_v [1u<<22];
__device__ __align__(128) float g_y [1u<<22];
__device__ __align__(128) float g_x [1u<<22];
__device__ __align__(128) float g_y2[1u<<22];
__device__ __align__(128) __nv_bfloat16 g_qkin_h[1u<<22], g_qkin_l[1u<<22];
__device__ __align__(128) __nv_bfloat16 g_src_h [1u<<22], g_src_l [1u<<22];
__device__ __align__(128) __nv_bfloat16 g_ctx_h [1u<<22], g_ctx_l [1u<<22];
__device__ __align__(128) __nv_bfloat16 g_x_h   [1u<<22], g_x_l   [1u<<22];
__device__ __align__(128) __nv_bfloat16 g_ff_h  [1u<<24], g_ff_l  [1u<<24];
__device__ __align__(128) __nv_bfloat16 g_wt_h  [12u<<20], g_wt_l [12u<<20];

// ---------------------------------------------------------------- helpers
__device__ __forceinline__ uint32_t smem_u32(const void* p) {
    uint32_t a;
    asm("{ .reg .u64 t; cvta.to.shared.u64 t, %1; cvt.u32.u64 %0, t; }" : "=r"(a) : "l"(p));
    return a;
}
__device__ __forceinline__ void cp16(uint32_t dst, const void* src) {
    asm volatile("cp.async.cg.shared.global [%0], [%1], 16;"
                 :: "r"(dst), "l"(__cvta_generic_to_global(src)) : "memory");
}
#define CP_COMMIT() asm volatile("cp.async.commit_group;" ::: "memory")
#define CP_WAIT1()  asm volatile("cp.async.wait_group 1;"  ::: "memory")

#define LDSM4(r, addr) \
    asm volatile("ldmatrix.sync.aligned.m8n8.x4.shared.b16 {%0,%1,%2,%3}, [%4];" \
                 : "=r"((r)[0]), "=r"((r)[1]), "=r"((r)[2]), "=r"((r)[3]) : "r"(addr))

#define MMA16816(d, a, b) \
    asm volatile("mma.sync.aligned.m16n8k16.row.col.f32.bf16.bf16.f32 " \
                 "{%0,%1,%2,%3}, {%4,%5,%6,%7}, {%8,%9}, {%0,%1,%2,%3};" \
                 : "+f"((d)[0]), "+f"((d)[1]), "+f"((d)[2]), "+f"((d)[3]) \
                 : "r"((a)[0]), "r"((a)[1]), "r"((a)[2]), "r"((a)[3]), \
                   "r"((b)[0]), "r"((b)[1]))

__device__ __forceinline__ void split_store4(__nv_bfloat16* __restrict__ H,
                                             __nv_bfloat16* __restrict__ L, float4 v) {
    union { __nv_bfloat16 b[4]; uint2 u; } hv, lv;
    hv.b[0] = __float2bfloat16(v.x); lv.b[0] = __float2bfloat16(v.x - __bfloat162float(hv.b[0]));
    hv.b[1] = __float2bfloat16(v.y); lv.b[1] = __float2bfloat16(v.y - __bfloat162float(hv.b[1]));
    hv.b[2] = __float2bfloat16(v.z); lv.b[2] = __float2bfloat16(v.z - __bfloat162float(hv.b[2]));
    hv.b[3] = __float2bfloat16(v.w); lv.b[3] = __float2bfloat16(v.w - __bfloat162float(hv.b[3]));
    *(uint2*)H = hv.u;
    *(uint2*)L = lv.u;
}
__device__ __forceinline__ void split_store2(__nv_bfloat16* __restrict__ H,
                                             __nv_bfloat16* __restrict__ L,
                                             float x, float y) {
    union { __nv_bfloat16 b[2]; uint32_t u; } hv, lv;
    hv.b[0] = __float2bfloat16(x); lv.b[0] = __float2bfloat16(x - __bfloat162float(hv.b[0]));
    hv.b[1] = __float2bfloat16(y); lv.b[1] = __float2bfloat16(y - __bfloat162float(hv.b[1]));
    *(uint32_t*)H = hv.u;
    *(uint32_t*)L = lv.u;
}

// ================================================================ HMMA GEMM
// C[M,N] = act( A @ B^T + bias (+R) )
// A = Ah+Al [M,K] bf16 K-major; B = Bh+Bl [N,K] bf16 K-major.
// CTA 128x128, 256 threads (8 warps = 4m x 2n, warp tile 32x64),
// K chunks of 32, 3-stage cp.async pipeline, padded smem (80B rows).
#define ST      3
#define CHUNK   32
#define ROWB    80                 // bytes per smem row (40 bf16)
#define MATB    (128 * ROWB)       // 10240
#define STAGEB  (4 * MATB)         // 40960
#define GEMM_SMEM (ST * STAGEB)    // 122880

template<bool RELU, bool RESID, bool SPLIT>
__global__ __launch_bounds__(256, 1)
void gemm_tc(const __nv_bfloat16* __restrict__ Ah, const __nv_bfloat16* __restrict__ Al,
             const __nv_bfloat16* __restrict__ Bh, const __nv_bfloat16* __restrict__ Bl,
             const float* __restrict__ bias, const float* __restrict__ Rsd,
             float* __restrict__ Cf, __nv_bfloat16* __restrict__ Ch, __nv_bfloat16* __restrict__ Cl,
             int M, int N, int K)
{
    extern __shared__ __align__(128) char smem[];
    const uint32_t sb = smem_u32(smem);
    const int tid  = threadIdx.x;
    const int wid  = tid >> 5, lane = tid & 31;
    const int bm   = blockIdx.y * 128, bn = blockIdx.x * 128;
    const int m0   = (wid & 3) * 32;         // warp row offset in tile
    const int n0   = (wid >> 2) * 64;        // warp col offset in tile
    const int nt   = K / CHUNK;

    float acc[2][8][4];
    #pragma unroll
    for (int i = 0; i < 2; i++)
        #pragma unroll
        for (int j = 0; j < 8; j++)
            #pragma unroll
            for (int q = 0; q < 4; q++) acc[i][j][q] = 0.f;

    auto stage = [&](int c) {
        const uint32_t base = sb + (uint32_t)(c % ST) * STAGEB;
        const size_t kof = (size_t)c * CHUNK;
        #pragma unroll
        for (int i = 0; i < 2; i++) {
            const int f   = tid + i * 256;      // 0..511
            const int row = f >> 2, ch = f & 3;
            const uint32_t so = row * ROWB + ch * 16;
            const size_t ga = (size_t)(bm + row) * K + kof + ch * 8;
            const size_t gb = (size_t)(bn + row) * K + kof + ch * 8;
            cp16(base +            so, Ah + ga);
            cp16(base +     MATB + so, Al + ga);
            cp16(base + 2 * MATB + so, Bh + gb);
            cp16(base + 3 * MATB + so, Bl + gb);
        }
        CP_COMMIT();
    };

    stage(0);
    stage(1);

    // per-lane ldmatrix address components
    const uint32_t a_row  = m0 + (lane & 15);
    const uint32_t a_coff = (uint32_t)((lane >> 4) << 4);              // bytes
    const uint32_t b_row  = n0 + ((lane >> 4) << 3) + (lane & 7);
    const uint32_t b_coff = (uint32_t)(((lane >> 3) & 1) << 4);        // bytes

    for (int c = 0; c < nt; c++) {
        if (c + ST - 1 < nt) stage(c + ST - 1);
        else                 CP_COMMIT();
        CP_WAIT1();
        __syncthreads();

        const uint32_t base = sb + (uint32_t)(c % ST) * STAGEB;
        #pragma unroll
        for (int ks = 0; ks < 2; ks++) {
            uint32_t aH[2][4], aL[2][4], bH[8][2], bL[8][2];
            #pragma unroll
            for (int mi = 0; mi < 2; mi++) {
                const uint32_t ra = base + (a_row + mi * 16) * ROWB + ks * 32 + a_coff;
                LDSM4(aH[mi], ra);
                LDSM4(aL[mi], ra + MATB);
            }
            #pragma unroll
            for (int t = 0; t < 4; t++) {
                const uint32_t rb = base + 2 * MATB + (b_row + t * 16) * ROWB + ks * 32 + b_coff;
                uint32_t r[4];
                LDSM4(r, rb);
                bH[2*t][0] = r[0]; bH[2*t][1] = r[1];
                bH[2*t+1][0] = r[2]; bH[2*t+1][1] = r[3];
                LDSM4(r, rb + MATB);
                bL[2*t][0] = r[0]; bL[2*t][1] = r[1];
                bL[2*t+1][0] = r[2]; bL[2*t+1][1] = r[3];
            }
            #pragma unroll
            for (int mi = 0; mi < 2; mi++)
                #pragma unroll
                for (int ni = 0; ni < 8; ni++) {
                    MMA16816(acc[mi][ni], aH[mi], bH[ni]);
                    MMA16816(acc[mi][ni], aL[mi], bH[ni]);
                    MMA16816(acc[mi][ni], aH[mi], bL[ni]);
                }
        }
        __syncthreads();
    }

    // epilogue: fragment -> global
    #pragma unroll
    for (int mi = 0; mi < 2; mi++) {
        #pragma unroll
        for (int half = 0; half < 2; half++) {
            const int r = bm + m0 + mi * 16 + half * 8 + (lane >> 2);
            const size_t orow = (size_t)r * N;
            #pragma unroll
            for (int ni = 0; ni < 8; ni++) {
                const int cc = bn + n0 + ni * 8 + (lane & 3) * 2;
                float vx = acc[mi][ni][half * 2 + 0];
                float vy = acc[mi][ni][half * 2 + 1];
                const float2 b2 = *(const float2*)(bias + cc);
                vx += b2.x; vy += b2.y;
                if constexpr (RESID) {
                    const float2 rr = *(const float2*)(Rsd + orow + cc);
                    vx += rr.x; vy += rr.y;
                }
                if constexpr (RELU) { vx = fmaxf(vx, 0.f); vy = fmaxf(vy, 0.f); }
                if constexpr (SPLIT) split_store2(Ch + orow + cc, Cl + orow + cc, vx, vy);
                else { float2 o; o.x = vx; o.y = vy; *(float2*)(Cf + orow + cc) = o; }
            }
        }
    }
}

// ================================================================ weight transpose+split
// W[K,N] fp32 -> Th,Tl[N,K] bf16
__global__ __launch_bounds__(256)
void tsplit_kernel(const float* __restrict__ W, __nv_bfloat16* __restrict__ Th,
                   __nv_bfloat16* __restrict__ Tl, int K, int N)
{
    __shared__ float t[32][33];
    const int n0 = blockIdx.x * 32, k0 = blockIdx.y * 32;
    const int tx = threadIdx.x, ty = threadIdx.y;
    #pragma unroll
    for (int i = 0; i < 32; i += 8)
        t[ty + i][tx] = W[(size_t)(k0 + ty + i) * N + n0 + tx];
    __syncthreads();
    #pragma unroll
    for (int i = 0; i < 32; i += 8) {
        const float v = t[tx][ty + i];
        const __nv_bfloat16 h = __float2bfloat16(v);
        const __nv_bfloat16 l = __float2bfloat16(v - __bfloat162float(h));
        const size_t o = (size_t)(n0 + ty + i) * K + k0 + tx;
        Th[o] = h; Tl[o] = l;
    }
}

// activation split (optionally a+b first)
template<bool ADD>
__global__ __launch_bounds__(256)
void split_kernel(const float* __restrict__ a, const float* __restrict__ b,
                  __nv_bfloat16* __restrict__ H, __nv_bfloat16* __restrict__ L)
{
    const size_t i = ((size_t)blockIdx.x * 256 + threadIdx.x) * 4;
    float4 v = *(const float4*)(a + i);
    if constexpr (ADD) {
        const float4 w = *(const float4*)(b + i);
        v.x += w.x; v.y += w.y; v.z += w.z; v.w += w.w;
    }
    split_store4(H + i, L + i, v);
}

// ================================================================ flash attention (fp32 SIMT)
__global__ __launch_bounds__(128, 2)
void attn_kernel(const float* __restrict__ Q, const float* __restrict__ Kp,
                 const float* __restrict__ V, const float* __restrict__ corr,
                 __nv_bfloat16* __restrict__ ctx_h, __nv_bfloat16* __restrict__ ctx_l)
{
    __shared__ float Ks[32][64];
    __shared__ float Vs[32][64];
    __shared__ float Cs[128][33];

    const int tid = threadIdx.x;
    const int q0  = blockIdx.x * 128;
    const int b   = blockIdx.y >> 4;
    const int h   = blockIdx.y & 15;

    const size_t qbase = ((size_t)(b * 2048 + q0 + tid)) * 1024 + h * 64;
    float Qr[64];
    #pragma unroll
    for (int i = 0; i < 16; i++) {
        const float4 t = *(const float4*)(Q + qbase + i * 4);
        Qr[i*4+0] = t.x * 0.125f;  Qr[i*4+1] = t.y * 0.125f;
        Qr[i*4+2] = t.z * 0.125f;  Qr[i*4+3] = t.w * 0.125f;
    }
    float Or[64];
    #pragma unroll
    for (int d = 0; d < 64; d++) Or[d] = 0.f;
    float m = -1e30f, l = 0.f;

    const size_t kvbase = (size_t)b * 2048 * 1024 + h * 64;
    const size_t cbase  = ((size_t)b * 2048 + q0) * 2048;

    for (int k0 = 0; k0 < 2048; k0 += 32) {
        #pragma unroll
        for (int i = 0; i < 4; i++) {
            const int f = tid + i * 128;
            const int row = f >> 4;
            const int c4  = (f & 15) << 2;
            const size_t g = kvbase + (size_t)(k0 + row) * 1024 + c4;
            *(float4*)&Ks[row][c4] = *(const float4*)(Kp + g);
            *(float4*)&Vs[row][c4] = *(const float4*)(V + g);
        }
        #pragma unroll
        for (int i = 0; i < 8; i++) {
            const int f = tid + i * 128;
            const int row = f >> 3;
            const int c4  = (f & 7) << 2;
            const float4 cv = *(const float4*)(corr + cbase + (size_t)row * 2048 + k0 + c4);
            Cs[row][c4+0] = cv.x; Cs[row][c4+1] = cv.y;
            Cs[row][c4+2] = cv.z; Cs[row][c4+3] = cv.w;
        }
        __syncthreads();

        #pragma unroll 2
        for (int j = 0; j < 32; j++) {
            const float4* kr = (const float4*)Ks[j];
            float s0 = Cs[tid][j], s1 = 0.f, s2 = 0.f, s3 = 0.f;
            #pragma unroll
            for (int d4 = 0; d4 < 16; d4++) {
                const float4 kv = kr[d4];
                s0 += Qr[d4*4+0] * kv.x;
                s1 += Qr[d4*4+1] * kv.y;
                s2 += Qr[d4*4+2] * kv.z;
                s3 += Qr[d4*4+3] * kv.w;
            }
            const float s = (s0 + s1) + (s2 + s3);
            float p;
            if (s > m) {
                const float sc = __expf(m - s);
                l *= sc;
                #pragma unroll
                for (int d = 0; d < 64; d++) Or[d] *= sc;
                m = s;
                p = 1.f;
            } else {
                p = __expf(s - m);
            }
            l += p;
            const float4* vr = (const float4*)Vs[j];
            #pragma unroll
            for (int d4 = 0; d4 < 16; d4++) {
                const float4 vv = vr[d4];
                Or[d4*4+0] += p * vv.x;
                Or[d4*4+1] += p * vv.y;
                Or[d4*4+2] += p * vv.z;
                Or[d4*4+3] += p * vv.w;
            }
        }
        __syncthreads();
    }

    const float inv = 1.f / l;
    #pragma unroll
    for (int i = 0; i < 16; i++) {
        float4 o;
        o.x = Or[i*4+0] * inv;  o.y = Or[i*4+1] * inv;
        o.z = Or[i*4+2] * inv;  o.w = Or[i*4+3] * inv;
        split_store4(ctx_h + qbase + i * 4, ctx_l + qbase + i * 4, o);
    }
}

// ================================================================ LayerNorm (optional bf16 split out)
template<bool SPLIT>
__global__ __launch_bounds__(256)
void ln_kernel(const float* __restrict__ in, const float* __restrict__ g,
               const float* __restrict__ b, float* __restrict__ out,
               __nv_bfloat16* __restrict__ H, __nv_bfloat16* __restrict__ L)
{
    __shared__ float rs[8], rq[8];
    const int tid = threadIdx.x;
    const size_t base = (size_t)blockIdx.x * 1024;

    const float4 v = *(const float4*)(in + base + tid * 4);
    float s  = v.x + v.y + v.z + v.w;
    float q2 = v.x*v.x + v.y*v.y + v.z*v.z + v.w*v.w;
    #pragma unroll
    for (int o = 16; o > 0; o >>= 1) {
        s  += __shfl_xor_sync(0xffffffffu, s,  o);
        q2 += __shfl_xor_sync(0xffffffffu, q2, o);
    }
    if ((tid & 31) == 0) { rs[tid >> 5] = s; rq[tid >> 5] = q2; }
    __syncthreads();
    float ts = 0.f, tq = 0.f;
    #pragma unroll
    for (int w = 0; w < 8; w++) { ts += rs[w]; tq += rq[w]; }

    const float mu   = ts * (1.f / 1024.f);
    const float var  = tq * (1.f / 1024.f) - mu * mu;
    const float invs = rsqrtf(var + 1e-5f);

    const float4 gg = *(const float4*)(g + tid * 4);
    const float4 bb = *(const float4*)(b + tid * 4);
    float4 o;
    o.x = (v.x - mu) * invs * gg.x + bb.x;
    o.y = (v.y - mu) * invs * gg.y + bb.y;
    o.z = (v.z - mu) * invs * gg.z + bb.z;
    o.w = (v.w - mu) * invs * gg.w + bb.w;
    *(float4*)(out + base + tid * 4) = o;
    if constexpr (SPLIT) split_store4(H + base + tid * 4, L + base + tid * 4, o);
}

// ================================================================ launch
extern "C" void kernel_launch(void* const* d_in, const int* in_sizes, int n_in,
                              void* d_out, int out_size)
{
    (void)in_sizes; (void)n_in; (void)out_size;
    const float* src  = (const float*)d_in[0];
    const float* corr = (const float*)d_in[1];
    const float* pos  = (const float*)d_in[2];
    const float* Wq   = (const float*)d_in[3];
    const float* bq   = (const float*)d_in[4];
    const float* Wk   = (const float*)d_in[5];
    const float* bk   = (const float*)d_in[6];
    const float* Wv   = (const float*)d_in[7];
    const float* bv   = (const float*)d_in[8];
    const float* Wo   = (const float*)d_in[9];
    const float* bo   = (const float*)d_in[10];
    const float* W1   = (const float*)d_in[11];
    const float* b1   = (const float*)d_in[12];
    const float* W2   = (const float*)d_in[13];
    const float* b2   = (const float*)d_in[14];
    const float* g1   = (const float*)d_in[15];
    const float* be1  = (const float*)d_in[16];
    const float* g2   = (const float*)d_in[17];
    const float* be2  = (const float*)d_in[18];
    float* out = (float*)d_out;

    float *q, *k, *v, *y, *x, *y2;
    __nv_bfloat16 *qkh, *qkl, *sh, *sl, *cth, *ctl, *xh, *xl, *ffh, *ffl, *wth, *wtl;
    cudaGetSymbolAddress((void**)&q,   g_q);    cudaGetSymbolAddress((void**)&k,   g_k);
    cudaGetSymbolAddress((void**)&v,   g_v);    cudaGetSymbolAddress((void**)&y,   g_y);
    cudaGetSymbolAddress((void**)&x,   g_x);    cudaGetSymbolAddress((void**)&y2,  g_y2);
    cudaGetSymbolAddress((void**)&qkh, g_qkin_h); cudaGetSymbolAddress((void**)&qkl, g_qkin_l);
    cudaGetSymbolAddress((void**)&sh,  g_src_h);  cudaGetSymbolAddress((void**)&sl,  g_src_l);
    cudaGetSymbolAddress((void**)&cth, g_ctx_h);  cudaGetSymbolAddress((void**)&ctl, g_ctx_l);
    cudaGetSymbolAddress((void**)&xh,  g_x_h);    cudaGetSymbolAddress((void**)&xl,  g_x_l);
    cudaGetSymbolAddress((void**)&ffh, g_ff_h);   cudaGetSymbolAddress((void**)&ffl, g_ff_l);
    cudaGetSymbolAddress((void**)&wth, g_wt_h);   cudaGetSymbolAddress((void**)&wtl, g_wt_l);

    // packed transposed-weight offsets (elements)
    const size_t OQ = 0, OK_ = 1u<<20, OV = 2u<<20, OO = 3u<<20, O1 = 4u<<20, O2 = 8u<<20;

    cudaFuncSetAttribute(gemm_tc<false,false,false>, cudaFuncAttributeMaxDynamicSharedMemorySize, GEMM_SMEM);
    cudaFuncSetAttribute(gemm_tc<false,true ,false>, cudaFuncAttributeMaxDynamicSharedMemorySize, GEMM_SMEM);
    cudaFuncSetAttribute(gemm_tc<true ,false,true >, cudaFuncAttributeMaxDynamicSharedMemorySize, GEMM_SMEM);

    const dim3 tb(32, 8);
    // weight transpose+split
    tsplit_kernel<<<dim3(1024/32, 1024/32), tb>>>(Wq, wth + OQ,  wtl + OQ,  1024, 1024);
    tsplit_kernel<<<dim3(1024/32, 1024/32), tb>>>(Wk, wth + OK_, wtl + OK_, 1024, 1024);
    tsplit_kernel<<<dim3(1024/32, 1024/32), tb>>>(Wv, wth + OV,  wtl + OV,  1024, 1024);
    tsplit_kernel<<<dim3(1024/32, 1024/32), tb>>>(Wo, wth + OO,  wtl + OO,  1024, 1024);
    tsplit_kernel<<<dim3(4096/32, 1024/32), tb>>>(W1, wth + O1,  wtl + O1,  1024, 4096);
    tsplit_kernel<<<dim3(1024/32, 4096/32), tb>>>(W2, wth + O2,  wtl + O2,  4096, 1024);

    // activation splits
    split_kernel<true ><<<4096, 256>>>(src, pos,     qkh, qkl);   // q/k input = src + pos
    split_kernel<false><<<4096, 256>>>(src, nullptr, sh,  sl);    // v input = src

    const dim3 gP(8, 32), gF1(32, 32);
    // projections
    gemm_tc<false,false,false><<<gP, 256, GEMM_SMEM>>>(qkh, qkl, wth + OQ,  wtl + OQ,  bq, nullptr, q,  nullptr, nullptr, 4096, 1024, 1024);
    gemm_tc<false,false,false><<<gP, 256, GEMM_SMEM>>>(qkh, qkl, wth + OK_, wtl + OK_, bk, nullptr, k,  nullptr, nullptr, 4096, 1024, 1024);
    gemm_tc<false,false,false><<<gP, 256, GEMM_SMEM>>>(sh,  sl,  wth + OV,  wtl + OV,  bv, nullptr, v,  nullptr, nullptr, 4096, 1024, 1024);

    attn_kernel<<<dim3(2048/128, 32), 128>>>(q, k, v, corr, cth, ctl);

    // output projection + residual(src) -> y ; LN1 -> x (+ bf16 split)
    gemm_tc<false,true ,false><<<gP, 256, GEMM_SMEM>>>(cth, ctl, wth + OO, wtl + OO, bo, src, y, nullptr, nullptr, 4096, 1024, 1024);
    ln_kernel<true ><<<4096, 256>>>(y, g1, be1, x, xh, xl);

    // FFN1: relu -> bf16 split directly ; FFN2 + residual(x) -> y2 ; LN2 -> out
    gemm_tc<true ,false,true ><<<gF1, 256, GEMM_SMEM>>>(xh,  xl,  wth + O1, wtl + O1, b1, nullptr, nullptr, ffh, ffl, 4096, 4096, 1024);
    gemm_tc<false,true ,false><<<gP,  256, GEMM_SMEM>>>(ffh, ffl, wth + O2, wtl + O2, b2, x,       y2, nullptr, nullptr, 4096, 1024, 4096);
    ln_kernel<false><<<4096, 256>>>(y2, g2, be2, out, nullptr, nullptr);
}

// round 9
// speedup vs baseline: 1.6578x; 1.6565x over previous
#include <cuda_runtime.h>
#include <cuda_bf16.h>
#include <math.h>
#include <stdint.h>

// B=2, S=2048, D_MODEL=1024, HEADS=16, D_K=64, D_FF=4096, tokens M=4096

// ---------------------------------------------------------------- scratch
__device__ __align__(128) float g_y [1u<<22];
__device__ __align__(128) float g_x [1u<<22];
__device__ __align__(128) float g_y2[1u<<22];
__device__ __align__(128) __nv_bfloat16 g_qkin_h[1u<<22], g_qkin_l[1u<<22];
__device__ __align__(128) __nv_bfloat16 g_src_h [1u<<22], g_src_l [1u<<22];
__device__ __align__(128) __nv_bfloat16 g_qb_h  [1u<<22], g_qb_l  [1u<<22];
__device__ __align__(128) __nv_bfloat16 g_kb_h  [1u<<22], g_kb_l  [1u<<22];
__device__ __align__(128) __nv_bfloat16 g_vb_h  [1u<<22], g_vb_l  [1u<<22];
__device__ __align__(128) __nv_bfloat16 g_ctx_h [1u<<22], g_ctx_l [1u<<22];
__device__ __align__(128) __nv_bfloat16 g_x_h   [1u<<22], g_x_l   [1u<<22];
__device__ __align__(128) __nv_bfloat16 g_ff_h  [1u<<24], g_ff_l  [1u<<24];
__device__ __align__(128) __nv_bfloat16 g_wt_h  [12u<<20], g_wt_l [12u<<20];

// ---------------------------------------------------------------- helpers
__device__ __forceinline__ uint32_t smem_u32(const void* p) {
    uint32_t a;
    asm("{ .reg .u64 t; cvta.to.shared.u64 t, %1; cvt.u32.u64 %0, t; }" : "=r"(a) : "l"(p));
    return a;
}
__device__ __forceinline__ void cp16(uint32_t dst, const void* src) {
    asm volatile("cp.async.cg.shared.global [%0], [%1], 16;"
                 :: "r"(dst), "l"(__cvta_generic_to_global(src)) : "memory");
}
#define CP_COMMIT() asm volatile("cp.async.commit_group;" ::: "memory")
#define CP_WAIT1()  asm volatile("cp.async.wait_group 1;"  ::: "memory")
#define CP_WAIT0()  asm volatile("cp.async.wait_group 0;"  ::: "memory")

#define LDSM4(r, addr) \
    asm volatile("ldmatrix.sync.aligned.m8n8.x4.shared.b16 {%0,%1,%2,%3}, [%4];" \
                 : "=r"((r)[0]), "=r"((r)[1]), "=r"((r)[2]), "=r"((r)[3]) : "r"(addr))
#define LDSM4T(r, addr) \
    asm volatile("ldmatrix.sync.aligned.m8n8.x4.trans.shared.b16 {%0,%1,%2,%3}, [%4];" \
                 : "=r"((r)[0]), "=r"((r)[1]), "=r"((r)[2]), "=r"((r)[3]) : "r"(addr))

#define MMA16816(d, a, b) \
    asm volatile("mma.sync.aligned.m16n8k16.row.col.f32.bf16.bf16.f32 " \
                 "{%0,%1,%2,%3}, {%4,%5,%6,%7}, {%8,%9}, {%0,%1,%2,%3};" \
                 : "+f"((d)[0]), "+f"((d)[1]), "+f"((d)[2]), "+f"((d)[3]) \
                 : "r"((a)[0]), "r"((a)[1]), "r"((a)[2]), "r"((a)[3]), \
                   "r"((b)[0]), "r"((b)[1]))

__device__ __forceinline__ void split_store4(__nv_bfloat16* __restrict__ H,
                                             __nv_bfloat16* __restrict__ L, float4 v) {
    union { __nv_bfloat16 b[4]; uint2 u; } hv, lv;
    hv.b[0] = __float2bfloat16(v.x); lv.b[0] = __float2bfloat16(v.x - __bfloat162float(hv.b[0]));
    hv.b[1] = __float2bfloat16(v.y); lv.b[1] = __float2bfloat16(v.y - __bfloat162float(hv.b[1]));
    hv.b[2] = __float2bfloat16(v.z); lv.b[2] = __float2bfloat16(v.z - __bfloat162float(hv.b[2]));
    hv.b[3] = __float2bfloat16(v.w); lv.b[3] = __float2bfloat16(v.w - __bfloat162float(hv.b[3]));
    *(uint2*)H = hv.u;
    *(uint2*)L = lv.u;
}
__device__ __forceinline__ void split_store2(__nv_bfloat16* __restrict__ H,
                                             __nv_bfloat16* __restrict__ L,
                                             float x, float y) {
    union { __nv_bfloat16 b[2]; uint32_t u; } hv, lv;
    hv.b[0] = __float2bfloat16(x); lv.b[0] = __float2bfloat16(x - __bfloat162float(hv.b[0]));
    hv.b[1] = __float2bfloat16(y); lv.b[1] = __float2bfloat16(y - __bfloat162float(hv.b[1]));
    *(uint32_t*)H = hv.u;
    *(uint32_t*)L = lv.u;
}
// pack (x lo, y hi) to bf16x2 + residual pair
__device__ __forceinline__ void packPS(float x, float y, uint32_t& ph, uint32_t& pl) {
    asm("cvt.rn.bf16x2.f32 %0, %1, %2;" : "=r"(ph) : "f"(y), "f"(x));
    const float rx = x - __uint_as_float(ph << 16);
    const float ry = y - __uint_as_float(ph & 0xffff0000u);
    asm("cvt.rn.bf16x2.f32 %0, %1, %2;" : "=r"(pl) : "f"(ry), "f"(rx));
}

// ================================================================ HMMA GEMM
#define ST      3
#define CHUNK   32
#define ROWB    80
#define MATB    (128 * ROWB)
#define STAGEB  (4 * MATB)
#define GEMM_SMEM (ST * STAGEB)

template<bool RELU, bool RESID, bool SPLIT>
__global__ __launch_bounds__(256, 1)
void gemm_tc(const __nv_bfloat16* __restrict__ Ah, const __nv_bfloat16* __restrict__ Al,
             const __nv_bfloat16* __restrict__ Bh, const __nv_bfloat16* __restrict__ Bl,
             const float* __restrict__ bias, const float* __restrict__ Rsd,
             float* __restrict__ Cf, __nv_bfloat16* __restrict__ Ch, __nv_bfloat16* __restrict__ Cl,
             int M, int N, int K)
{
    extern __shared__ __align__(128) char smem[];
    const uint32_t sb = smem_u32(smem);
    const int tid  = threadIdx.x;
    const int wid  = tid >> 5, lane = tid & 31;
    const int bm   = blockIdx.y * 128, bn = blockIdx.x * 128;
    const int m0   = (wid & 3) * 32;
    const int n0   = (wid >> 2) * 64;
    const int nt   = K / CHUNK;

    float acc[2][8][4];
    #pragma unroll
    for (int i = 0; i < 2; i++)
        #pragma unroll
        for (int j = 0; j < 8; j++)
            #pragma unroll
            for (int q = 0; q < 4; q++) acc[i][j][q] = 0.f;

    auto stage = [&](int c) {
        const uint32_t base = sb + (uint32_t)(c % ST) * STAGEB;
        const size_t kof = (size_t)c * CHUNK;
        #pragma unroll
        for (int i = 0; i < 2; i++) {
            const int f   = tid + i * 256;
            const int row = f >> 2, ch = f & 3;
            const uint32_t so = row * ROWB + ch * 16;
            const size_t ga = (size_t)(bm + row) * K + kof + ch * 8;
            const size_t gb = (size_t)(bn + row) * K + kof + ch * 8;
            cp16(base +            so, Ah + ga);
            cp16(base +     MATB + so, Al + ga);
            cp16(base + 2 * MATB + so, Bh + gb);
            cp16(base + 3 * MATB + so, Bl + gb);
        }
        CP_COMMIT();
    };

    stage(0);
    stage(1);

    const uint32_t a_row  = m0 + (lane & 15);
    const uint32_t a_coff = (uint32_t)((lane >> 4) << 4);
    const uint32_t b_row  = n0 + ((lane >> 4) << 3) + (lane & 7);
    const uint32_t b_coff = (uint32_t)(((lane >> 3) & 1) << 4);

    for (int c = 0; c < nt; c++) {
        if (c + ST - 1 < nt) stage(c + ST - 1);
        else                 CP_COMMIT();
        CP_WAIT1();
        __syncthreads();

        const uint32_t base = sb + (uint32_t)(c % ST) * STAGEB;
        #pragma unroll
        for (int ks = 0; ks < 2; ks++) {
            uint32_t aH[2][4], aL[2][4], bH[8][2], bL[8][2];
            #pragma unroll
            for (int mi = 0; mi < 2; mi++) {
                const uint32_t ra = base + (a_row + mi * 16) * ROWB + ks * 32 + a_coff;
                LDSM4(aH[mi], ra);
                LDSM4(aL[mi], ra + MATB);
            }
            #pragma unroll
            for (int t = 0; t < 4; t++) {
                const uint32_t rb = base + 2 * MATB + (b_row + t * 16) * ROWB + ks * 32 + b_coff;
                uint32_t r[4];
                LDSM4(r, rb);
                bH[2*t][0] = r[0]; bH[2*t][1] = r[1];
                bH[2*t+1][0] = r[2]; bH[2*t+1][1] = r[3];
                LDSM4(r, rb + MATB);
                bL[2*t][0] = r[0]; bL[2*t][1] = r[1];
                bL[2*t+1][0] = r[2]; bL[2*t+1][1] = r[3];
            }
            #pragma unroll
            for (int mi = 0; mi < 2; mi++)
                #pragma unroll
                for (int ni = 0; ni < 8; ni++) {
                    MMA16816(acc[mi][ni], aH[mi], bH[ni]);
                    MMA16816(acc[mi][ni], aL[mi], bH[ni]);
                    MMA16816(acc[mi][ni], aH[mi], bL[ni]);
                }
        }
        __syncthreads();
    }

    #pragma unroll
    for (int mi = 0; mi < 2; mi++) {
        #pragma unroll
        for (int half = 0; half < 2; half++) {
            const int r = bm + m0 + mi * 16 + half * 8 + (lane >> 2);
            const size_t orow = (size_t)r * N;
            #pragma unroll
            for (int ni = 0; ni < 8; ni++) {
                const int cc = bn + n0 + ni * 8 + (lane & 3) * 2;
                float vx = acc[mi][ni][half * 2 + 0];
                float vy = acc[mi][ni][half * 2 + 1];
                const float2 b2 = *(const float2*)(bias + cc);
                vx += b2.x; vy += b2.y;
                if constexpr (RESID) {
                    const float2 rr = *(const float2*)(Rsd + orow + cc);
                    vx += rr.x; vy += rr.y;
                }
                if constexpr (RELU) { vx = fmaxf(vx, 0.f); vy = fmaxf(vy, 0.f); }
                if constexpr (SPLIT) split_store2(Ch + orow + cc, Cl + orow + cc, vx, vy);
                else { float2 o; o.x = vx; o.y = vy; *(float2*)(Cf + orow + cc) = o; }
            }
        }
    }
}

// ================================================================ weight transpose+split
__global__ __launch_bounds__(256)
void tsplit_kernel(const float* __restrict__ W, __nv_bfloat16* __restrict__ Th,
                   __nv_bfloat16* __restrict__ Tl, int K, int N)
{
    __shared__ float t[32][33];
    const int n0 = blockIdx.x * 32, k0 = blockIdx.y * 32;
    const int tx = threadIdx.x, ty = threadIdx.y;
    #pragma unroll
    for (int i = 0; i < 32; i += 8)
        t[ty + i][tx] = W[(size_t)(k0 + ty + i) * N + n0 + tx];
    __syncthreads();
    #pragma unroll
    for (int i = 0; i < 32; i += 8) {
        const float v = t[tx][ty + i];
        const __nv_bfloat16 h = __float2bfloat16(v);
        const __nv_bfloat16 l = __float2bfloat16(v - __bfloat162float(h));
        const size_t o = (size_t)(n0 + ty + i) * K + k0 + tx;
        Th[o] = h; Tl[o] = l;
    }
}

template<bool ADD>
__global__ __launch_bounds__(256)
void split_kernel(const float* __restrict__ a, const float* __restrict__ b,
                  __nv_bfloat16* __restrict__ H, __nv_bfloat16* __restrict__ L)
{
    const size_t i = ((size_t)blockIdx.x * 256 + threadIdx.x) * 4;
    float4 v = *(const float4*)(a + i);
    if constexpr (ADD) {
        const float4 w = *(const float4*)(b + i);
        v.x += w.x; v.y += w.y; v.z += w.z; v.w += w.w;
    }
    split_store4(H + i, L + i, v);
}

// ================================================================ HMMA flash attention
// grid (S/128, B*H), 256 threads (8 warps, m16 each). kv tiles of 64.
// scores = (QhKh + QlKh + QhKl)/8 + corr ; P,V hi/lo 3-term PV. fp32 softmax.
// smem: 2 stages x { Kh,Kl,Vh,Vl : 64 rows x 144B } = 73728 B.
#define AT_STG  36864
#define AT_SMEM (2 * AT_STG)

__global__ __launch_bounds__(256, 1)
void attn_mma(const __nv_bfloat16* __restrict__ Qh, const __nv_bfloat16* __restrict__ Ql,
              const __nv_bfloat16* __restrict__ Kh, const __nv_bfloat16* __restrict__ Kl,
              const __nv_bfloat16* __restrict__ Vh, const __nv_bfloat16* __restrict__ Vl,
              const float* __restrict__ corr,
              __nv_bfloat16* __restrict__ ctx_h, __nv_bfloat16* __restrict__ ctx_l)
{
    extern __shared__ __align__(128) char smem[];
    const uint32_t sb = smem_u32(smem);
    const int tid = threadIdx.x, wid = tid >> 5, lane = tid & 31;
    const int q0 = blockIdx.x * 128;
    const int b  = blockIdx.y >> 4, h = blockIdx.y & 15;
    const size_t tok0 = (size_t)b * 2048;

    // ---- stage Q (hi/lo) into stage0 region, load a-fragments, release ----
    #pragma unroll
    for (int i = 0; i < 4; i++) {
        const int f = tid + i * 256;           // 0..1023
        const int row = f >> 3, ch = f & 7;
        const size_t g = (tok0 + q0 + row) * 1024 + h * 64 + ch * 8;
        cp16(sb +         row * 144 + ch * 16, Qh + g);
        cp16(sb + 18432 + row * 144 + ch * 16, Ql + g);
    }
    CP_COMMIT();
    CP_WAIT0();
    __syncthreads();

    uint32_t qh[4][4], ql[4][4];
    {
        const uint32_t ab = sb + (wid * 16 + (lane & 15)) * 144 + ((lane >> 4) << 4);
        #pragma unroll
        for (int ks = 0; ks < 4; ks++) {
            LDSM4(qh[ks], ab + ks * 32);
            LDSM4(ql[ks], ab + 18432 + ks * 32);
        }
    }
    __syncthreads();

    auto stageKV = [&](int c) {
        const uint32_t base = sb + (uint32_t)(c & 1) * AT_STG;
        const int k0 = c * 64;
        #pragma unroll
        for (int i = 0; i < 8; i++) {
            const int f   = tid + i * 256;     // 0..2047
            const int mat = f >> 9;            // 0..3
            const int idx = f & 511;
            const int row = idx >> 3, ch = idx & 7;
            const size_t g = (tok0 + k0 + row) * 1024 + h * 64 + ch * 8;
            const __nv_bfloat16* src = (mat == 0) ? Kh : (mat == 1) ? Kl : (mat == 2) ? Vh : Vl;
            cp16(base + mat * 9216 + row * 144 + ch * 16, src + g);
        }
        CP_COMMIT();
    };

    float o[8][4];
    #pragma unroll
    for (int d = 0; d < 8; d++)
        #pragma unroll
        for (int q = 0; q < 4; q++) o[d][q] = 0.f;
    float m0 = -1e30f, m1 = -1e30f, l0 = 0.f, l1 = 0.f;

    stageKV(0);

    const uint32_t brow  = ((lane >> 4) << 3) + (lane & 7);
    const uint32_t bcoff = ((lane >> 3) & 1) << 4;
    const int r   = lane >> 2;
    const int cc2 = (lane & 3) * 2;
    const float* corrb = corr + ((size_t)b * 2048 + q0 + wid * 16) * 2048;
    const uint32_t vlrow = ((lane >> 3) & 1) * 8 + (lane & 7);
    const uint32_t vlcol = (uint32_t)((lane >> 4) << 4);   // bytes: (lane>>4)*8 bf16

    for (int c = 0; c < 32; c++) {
        if (c + 1 < 32) stageKV(c + 1);
        else            CP_COMMIT();
        CP_WAIT1();
        __syncthreads();

        const uint32_t kb = sb + (uint32_t)(c & 1) * AT_STG;
        float s[8][4];
        #pragma unroll
        for (int j = 0; j < 8; j++)
            #pragma unroll
            for (int q = 0; q < 4; q++) s[j][q] = 0.f;

        // ---- S = Q K^T (3 terms) ----
        #pragma unroll
        for (int ks = 0; ks < 4; ks++) {
            #pragma unroll
            for (int tp = 0; tp < 4; tp++) {
                uint32_t bh[4], bl[4];
                const uint32_t ad = kb + (brow + tp * 16) * 144 + ks * 32 + bcoff;
                LDSM4(bh, ad);
                LDSM4(bl, ad + 9216);
                MMA16816(s[2*tp],   qh[ks], bh + 0);
                MMA16816(s[2*tp],   ql[ks], bh + 0);
                MMA16816(s[2*tp],   qh[ks], bl + 0);
                MMA16816(s[2*tp+1], qh[ks], bh + 2);
                MMA16816(s[2*tp+1], ql[ks], bh + 2);
                MMA16816(s[2*tp+1], qh[ks], bl + 2);
            }
        }

        // ---- scale + corr ----
        const int k0 = c * 64;
        #pragma unroll
        for (int j = 0; j < 8; j++) {
            const float2 c0 = *(const float2*)(corrb + (size_t)r       * 2048 + k0 + j * 8 + cc2);
            const float2 c1 = *(const float2*)(corrb + (size_t)(r + 8) * 2048 + k0 + j * 8 + cc2);
            s[j][0] = s[j][0] * 0.125f + c0.x;
            s[j][1] = s[j][1] * 0.125f + c0.y;
            s[j][2] = s[j][2] * 0.125f + c1.x;
            s[j][3] = s[j][3] * 0.125f + c1.y;
        }

        // ---- online softmax ----
        float mx0 = s[0][0], mx1 = s[0][2];
        #pragma unroll
        for (int j = 0; j < 8; j++) {
            mx0 = fmaxf(mx0, fmaxf(s[j][0], s[j][1]));
            mx1 = fmaxf(mx1, fmaxf(s[j][2], s[j][3]));
        }
        mx0 = fmaxf(mx0, __shfl_xor_sync(0xffffffffu, mx0, 1));
        mx0 = fmaxf(mx0, __shfl_xor_sync(0xffffffffu, mx0, 2));
        mx1 = fmaxf(mx1, __shfl_xor_sync(0xffffffffu, mx1, 1));
        mx1 = fmaxf(mx1, __shfl_xor_sync(0xffffffffu, mx1, 2));
        const float mn0 = fmaxf(m0, mx0), mn1 = fmaxf(m1, mx1);
        const float sc0 = __expf(m0 - mn0), sc1 = __expf(m1 - mn1);
        float sum0 = 0.f, sum1 = 0.f;
        #pragma unroll
        for (int j = 0; j < 8; j++) {
            s[j][0] = __expf(s[j][0] - mn0);
            s[j][1] = __expf(s[j][1] - mn0);
            s[j][2] = __expf(s[j][2] - mn1);
            s[j][3] = __expf(s[j][3] - mn1);
            sum0 += s[j][0] + s[j][1];
            sum1 += s[j][2] + s[j][3];
        }
        sum0 += __shfl_xor_sync(0xffffffffu, sum0, 1);
        sum0 += __shfl_xor_sync(0xffffffffu, sum0, 2);
        sum1 += __shfl_xor_sync(0xffffffffu, sum1, 1);
        sum1 += __shfl_xor_sync(0xffffffffu, sum1, 2);
        l0 = l0 * sc0 + sum0;
        l1 = l1 * sc1 + sum1;
        m0 = mn0; m1 = mn1;
        #pragma unroll
        for (int d = 0; d < 8; d++) {
            o[d][0] *= sc0; o[d][1] *= sc0;
            o[d][2] *= sc1; o[d][3] *= sc1;
        }

        // ---- O += P V (3 terms: PhVh + PlVh + PhVl) ----
        const uint32_t vb = kb + 18432;
        #pragma unroll
        for (int t = 0; t < 4; t++) {
            uint32_t ah[4], al[4];
            packPS(s[2*t][0],   s[2*t][1],   ah[0], al[0]);
            packPS(s[2*t][2],   s[2*t][3],   ah[1], al[1]);
            packPS(s[2*t+1][0], s[2*t+1][1], ah[2], al[2]);
            packPS(s[2*t+1][2], s[2*t+1][3], ah[3], al[3]);
            #pragma unroll
            for (int dp = 0; dp < 4; dp++) {
                uint32_t bvh[4], bvl[4];
                const uint32_t ad = vb + (t * 16 + vlrow) * 144 + dp * 32 + vlcol;
                LDSM4T(bvh, ad);
                LDSM4T(bvl, ad + 9216);
                MMA16816(o[2*dp],   ah, bvh + 0);
                MMA16816(o[2*dp],   al, bvh + 0);
                MMA16816(o[2*dp],   ah, bvl + 0);
                MMA16816(o[2*dp+1], ah, bvh + 2);
                MMA16816(o[2*dp+1], al, bvh + 2);
                MMA16816(o[2*dp+1], ah, bvl + 2);
            }
        }
        __syncthreads();
    }

    // ---- epilogue ----
    const float i0 = 1.f / l0, i1 = 1.f / l1;
    const size_t row0 = (tok0 + q0 + wid * 16 + r)     * 1024;
    const size_t row1 = (tok0 + q0 + wid * 16 + r + 8) * 1024;
    #pragma unroll
    for (int d = 0; d < 8; d++) {
        const int col = h * 64 + d * 8 + cc2;
        split_store2(ctx_h + row0 + col, ctx_l + row0 + col, o[d][0] * i0, o[d][1] * i0);
        split_store2(ctx_h + row1 + col, ctx_l + row1 + col, o[d][2] * i1, o[d][3] * i1);
    }
}

// ================================================================ LayerNorm
template<bool SPLIT>
__global__ __launch_bounds__(256)
void ln_kernel(const float* __restrict__ in, const float* __restrict__ g,
               const float* __restrict__ b, float* __restrict__ out,
               __nv_bfloat16* __restrict__ H, __nv_bfloat16* __restrict__ L)
{
    __shared__ float rs[8], rq[8];
    const int tid = threadIdx.x;
    const size_t base = (size_t)blockIdx.x * 1024;

    const float4 v = *(const float4*)(in + base + tid * 4);
    float s  = v.x + v.y + v.z + v.w;
    float q2 = v.x*v.x + v.y*v.y + v.z*v.z + v.w*v.w;
    #pragma unroll
    for (int o = 16; o > 0; o >>= 1) {
        s  += __shfl_xor_sync(0xffffffffu, s,  o);
        q2 += __shfl_xor_sync(0xffffffffu, q2, o);
    }
    if ((tid & 31) == 0) { rs[tid >> 5] = s; rq[tid >> 5] = q2; }
    __syncthreads();
    float ts = 0.f, tq = 0.f;
    #pragma unroll
    for (int w = 0; w < 8; w++) { ts += rs[w]; tq += rq[w]; }

    const float mu   = ts * (1.f / 1024.f);
    const float var  = tq * (1.f / 1024.f) - mu * mu;
    const float invs = rsqrtf(var + 1e-5f);

    const float4 gg = *(const float4*)(g + tid * 4);
    const float4 bb = *(const float4*)(b + tid * 4);
    float4 o;
    o.x = (v.x - mu) * invs * gg.x + bb.x;
    o.y = (v.y - mu) * invs * gg.y + bb.y;
    o.z = (v.z - mu) * invs * gg.z + bb.z;
    o.w = (v.w - mu) * invs * gg.w + bb.w;
    *(float4*)(out + base + tid * 4) = o;
    if constexpr (SPLIT) split_store4(H + base + tid * 4, L + base + tid * 4, o);
}

// ================================================================ launch
extern "C" void kernel_launch(void* const* d_in, const int* in_sizes, int n_in,
                              void* d_out, int out_size)
{
    (void)in_sizes; (void)n_in; (void)out_size;
    const float* src  = (const float*)d_in[0];
    const float* corr = (const float*)d_in[1];
    const float* pos  = (const float*)d_in[2];
    const float* Wq   = (const float*)d_in[3];
    const float* bq   = (const float*)d_in[4];
    const float* Wk   = (const float*)d_in[5];
    const float* bk   = (const float*)d_in[6];
    const float* Wv   = (const float*)d_in[7];
    const float* bv   = (const float*)d_in[8];
    const float* Wo   = (const float*)d_in[9];
    const float* bo   = (const float*)d_in[10];
    const float* W1   = (const float*)d_in[11];
    const float* b1   = (const float*)d_in[12];
    const float* W2   = (const float*)d_in[13];
    const float* b2   = (const float*)d_in[14];
    const float* g1   = (const float*)d_in[15];
    const float* be1  = (const float*)d_in[16];
    const float* g2   = (const float*)d_in[17];
    const float* be2  = (const float*)d_in[18];
    float* out = (float*)d_out;

    float *y, *x, *y2;
    __nv_bfloat16 *qkh, *qkl, *sh, *sl, *cth, *ctl, *xh, *xl, *ffh, *ffl, *wth, *wtl;
    __nv_bfloat16 *qbh, *qbl, *kbh, *kbl, *vbh, *vbl;
    cudaGetSymbolAddress((void**)&y,   g_y);      cudaGetSymbolAddress((void**)&x,   g_x);
    cudaGetSymbolAddress((void**)&y2,  g_y2);
    cudaGetSymbolAddress((void**)&qkh, g_qkin_h); cudaGetSymbolAddress((void**)&qkl, g_qkin_l);
    cudaGetSymbolAddress((void**)&sh,  g_src_h);  cudaGetSymbolAddress((void**)&sl,  g_src_l);
    cudaGetSymbolAddress((void**)&qbh, g_qb_h);   cudaGetSymbolAddress((void**)&qbl, g_qb_l);
    cudaGetSymbolAddress((void**)&kbh, g_kb_h);   cudaGetSymbolAddress((void**)&kbl, g_kb_l);
    cudaGetSymbolAddress((void**)&vbh, g_vb_h);   cudaGetSymbolAddress((void**)&vbl, g_vb_l);
    cudaGetSymbolAddress((void**)&cth, g_ctx_h);  cudaGetSymbolAddress((void**)&ctl, g_ctx_l);
    cudaGetSymbolAddress((void**)&xh,  g_x_h);    cudaGetSymbolAddress((void**)&xl,  g_x_l);
    cudaGetSymbolAddress((void**)&ffh, g_ff_h);   cudaGetSymbolAddress((void**)&ffl, g_ff_l);
    cudaGetSymbolAddress((void**)&wth, g_wt_h);   cudaGetSymbolAddress((void**)&wtl, g_wt_l);

    const size_t OQ = 0, OK_ = 1u<<20, OV = 2u<<20, OO = 3u<<20, O1 = 4u<<20, O2 = 8u<<20;

    cudaFuncSetAttribute(gemm_tc<false,false,true >, cudaFuncAttributeMaxDynamicSharedMemorySize, GEMM_SMEM);
    cudaFuncSetAttribute(gemm_tc<false,true ,false>, cudaFuncAttributeMaxDynamicSharedMemorySize, GEMM_SMEM);
    cudaFuncSetAttribute(gemm_tc<true ,false,true >, cudaFuncAttributeMaxDynamicSharedMemorySize, GEMM_SMEM);
    cudaFuncSetAttribute(attn_mma, cudaFuncAttributeMaxDynamicSharedMemorySize, AT_SMEM);

    const dim3 tb(32, 8);
    tsplit_kernel<<<dim3(1024/32, 1024/32), tb>>>(Wq, wth + OQ,  wtl + OQ,  1024, 1024);
    tsplit_kernel<<<dim3(1024/32, 1024/32), tb>>>(Wk, wth + OK_, wtl + OK_, 1024, 1024);
    tsplit_kernel<<<dim3(1024/32, 1024/32), tb>>>(Wv, wth + OV,  wtl + OV,  1024, 1024);
    tsplit_kernel<<<dim3(1024/32, 1024/32), tb>>>(Wo, wth + OO,  wtl + OO,  1024, 1024);
    tsplit_kernel<<<dim3(4096/32, 1024/32), tb>>>(W1, wth + O1,  wtl + O1,  1024, 4096);
    tsplit_kernel<<<dim3(1024/32, 4096/32), tb>>>(W2, wth + O2,  wtl + O2,  4096, 1024);

    split_kernel<true ><<<4096, 256>>>(src, pos,     qkh, qkl);
    split_kernel<false><<<4096, 256>>>(src, nullptr, sh,  sl);

    const dim3 gP(8, 32), gF1(32, 32);
    // projections -> bf16 hi/lo q,k,v
    gemm_tc<false,false,true ><<<gP, 256, GEMM_SMEM>>>(qkh, qkl, wth + OQ,  wtl + OQ,  bq, nullptr, nullptr, qbh, qbl, 4096, 1024, 1024);
    gemm_tc<false,false,true ><<<gP, 256, GEMM_SMEM>>>(qkh, qkl, wth + OK_, wtl + OK_, bk, nullptr, nullptr, kbh, kbl, 4096, 1024, 1024);
    gemm_tc<false,false,true ><<<gP, 256, GEMM_SMEM>>>(sh,  sl,  wth + OV,  wtl + OV,  bv, nullptr, nullptr, vbh, vbl, 4096, 1024, 1024);

    attn_mma<<<dim3(16, 32), 256, AT_SMEM>>>(qbh, qbl, kbh, kbl, vbh, vbl, corr, cth, ctl);

    gemm_tc<false,true ,false><<<gP, 256, GEMM_SMEM>>>(cth, ctl, wth + OO, wtl + OO, bo, src, y, nullptr, nullptr, 4096, 1024, 1024);
    ln_kernel<true ><<<4096, 256>>>(y, g1, be1, x, xh, xl);

    gemm_tc<true ,false,true ><<<gF1, 256, GEMM_SMEM>>>(xh,  xl,  wth + O1, wtl + O1, b1, nullptr, nullptr, ffh, ffl, 4096, 4096, 1024);
    gemm_tc<false,true ,false><<<gP,  256, GEMM_SMEM>>>(ffh, ffl, wth + O2, wtl + O2, b2, x,       y2, nullptr, nullptr, 4096, 1024, 4096);
    ln_kernel<false><<<4096, 256>>>(y2, g2, be2, out, nullptr, nullptr);
}

// round 10
// speedup vs baseline: 1.6615x; 1.0022x over previous
#include <cuda_runtime.h>
#include <cuda_bf16.h>
#include <math.h>
#include <stdint.h>

// B=2, S=2048, D_MODEL=1024, HEADS=16, D_K=64, D_FF=4096, tokens M=4096

// ---------------------------------------------------------------- scratch
__device__ __align__(128) float g_y [1u<<22];
__device__ __align__(128) float g_x [1u<<22];
__device__ __align__(128) float g_y2[1u<<22];
__device__ __align__(128) __nv_bfloat16 g_qkin_h[1u<<22], g_qkin_l[1u<<22];
__device__ __align__(128) __nv_bfloat16 g_src_h [1u<<22], g_src_l [1u<<22];
__device__ __align__(128) __nv_bfloat16 g_qb_h  [1u<<22], g_qb_l  [1u<<22];
__device__ __align__(128) __nv_bfloat16 g_kb_h  [1u<<22], g_kb_l  [1u<<22];
__device__ __align__(128) __nv_bfloat16 g_vb_h  [1u<<22], g_vb_l  [1u<<22];
__device__ __align__(128) __nv_bfloat16 g_ctx_h [1u<<22], g_ctx_l [1u<<22];
__device__ __align__(128) __nv_bfloat16 g_x_h   [1u<<22], g_x_l   [1u<<22];
__device__ __align__(128) __nv_bfloat16 g_ff_h  [1u<<24], g_ff_l  [1u<<24];
__device__ __align__(128) __nv_bfloat16 g_wt_h  [12u<<20], g_wt_l [12u<<20];

// ---------------------------------------------------------------- helpers
__device__ __forceinline__ uint32_t smem_u32(const void* p) {
    uint32_t a;
    asm("{ .reg .u64 t; cvta.to.shared.u64 t, %1; cvt.u32.u64 %0, t; }" : "=r"(a) : "l"(p));
    return a;
}
__device__ __forceinline__ void cp16(uint32_t dst, const void* src) {
    asm volatile("cp.async.cg.shared.global [%0], [%1], 16;"
                 :: "r"(dst), "l"(__cvta_generic_to_global(src)) : "memory");
}
#define CP_COMMIT() asm volatile("cp.async.commit_group;" ::: "memory")
#define CP_WAIT1()  asm volatile("cp.async.wait_group 1;"  ::: "memory")
#define CP_WAIT0()  asm volatile("cp.async.wait_group 0;"  ::: "memory")

#define LDSM4(r, addr) \
    asm volatile("ldmatrix.sync.aligned.m8n8.x4.shared.b16 {%0,%1,%2,%3}, [%4];" \
                 : "=r"((r)[0]), "=r"((r)[1]), "=r"((r)[2]), "=r"((r)[3]) : "r"(addr))
#define LDSM4T(r, addr) \
    asm volatile("ldmatrix.sync.aligned.m8n8.x4.trans.shared.b16 {%0,%1,%2,%3}, [%4];" \
                 : "=r"((r)[0]), "=r"((r)[1]), "=r"((r)[2]), "=r"((r)[3]) : "r"(addr))

#define MMA16816(d, a, b) \
    asm volatile("mma.sync.aligned.m16n8k16.row.col.f32.bf16.bf16.f32 " \
                 "{%0,%1,%2,%3}, {%4,%5,%6,%7}, {%8,%9}, {%0,%1,%2,%3};" \
                 : "+f"((d)[0]), "+f"((d)[1]), "+f"((d)[2]), "+f"((d)[3]) \
                 : "r"((a)[0]), "r"((a)[1]), "r"((a)[2]), "r"((a)[3]), \
                   "r"((b)[0]), "r"((b)[1]))

__device__ __forceinline__ void split_store4(__nv_bfloat16* __restrict__ H,
                                             __nv_bfloat16* __restrict__ L, float4 v) {
    union { __nv_bfloat16 b[4]; uint2 u; } hv, lv;
    hv.b[0] = __float2bfloat16(v.x); lv.b[0] = __float2bfloat16(v.x - __bfloat162float(hv.b[0]));
    hv.b[1] = __float2bfloat16(v.y); lv.b[1] = __float2bfloat16(v.y - __bfloat162float(hv.b[1]));
    hv.b[2] = __float2bfloat16(v.z); lv.b[2] = __float2bfloat16(v.z - __bfloat162float(hv.b[2]));
    hv.b[3] = __float2bfloat16(v.w); lv.b[3] = __float2bfloat16(v.w - __bfloat162float(hv.b[3]));
    *(uint2*)H = hv.u;
    *(uint2*)L = lv.u;
}
__device__ __forceinline__ void split_store2(__nv_bfloat16* __restrict__ H,
                                             __nv_bfloat16* __restrict__ L,
                                             float x, float y) {
    union { __nv_bfloat16 b[2]; uint32_t u; } hv, lv;
    hv.b[0] = __float2bfloat16(x); lv.b[0] = __float2bfloat16(x - __bfloat162float(hv.b[0]));
    hv.b[1] = __float2bfloat16(y); lv.b[1] = __float2bfloat16(y - __bfloat162float(hv.b[1]));
    *(uint32_t*)H = hv.u;
    *(uint32_t*)L = lv.u;
}
// pack (x lo, y hi) to bf16x2 + residual pair
__device__ __forceinline__ void packPS(float x, float y, uint32_t& ph, uint32_t& pl) {
    asm("cvt.rn.bf16x2.f32 %0, %1, %2;" : "=r"(ph) : "f"(y), "f"(x));
    const float rx = x - __uint_as_float(ph << 16);
    const float ry = y - __uint_as_float(ph & 0xffff0000u);
    asm("cvt.rn.bf16x2.f32 %0, %1, %2;" : "=r"(pl) : "f"(ry), "f"(rx));
}

// ================================================================ HMMA GEMM
#define ST      3
#define CHUNK   32
#define ROWB    80
#define MATB    (128 * ROWB)
#define STAGEB  (4 * MATB)
#define GEMM_SMEM (ST * STAGEB)

template<bool RELU, bool RESID, bool SPLIT>
__global__ __launch_bounds__(256, 1)
void gemm_tc(const __nv_bfloat16* __restrict__ Ah, const __nv_bfloat16* __restrict__ Al,
             const __nv_bfloat16* __restrict__ Bh, const __nv_bfloat16* __restrict__ Bl,
             const float* __restrict__ bias, const float* __restrict__ Rsd,
             float* __restrict__ Cf, __nv_bfloat16* __restrict__ Ch, __nv_bfloat16* __restrict__ Cl,
             int M, int N, int K)
{
    extern __shared__ __align__(128) char smem[];
    const uint32_t sb = smem_u32(smem);
    const int tid  = threadIdx.x;
    const int wid  = tid >> 5, lane = tid & 31;
    const int bm   = blockIdx.y * 128, bn = blockIdx.x * 128;
    const int m0   = (wid & 3) * 32;
    const int n0   = (wid >> 2) * 64;
    const int nt   = K / CHUNK;

    float acc[2][8][4];
    #pragma unroll
    for (int i = 0; i < 2; i++)
        #pragma unroll
        for (int j = 0; j < 8; j++)
            #pragma unroll
            for (int q = 0; q < 4; q++) acc[i][j][q] = 0.f;

    auto stage = [&](int c) {
        const uint32_t base = sb + (uint32_t)(c % ST) * STAGEB;
        const size_t kof = (size_t)c * CHUNK;
        #pragma unroll
        for (int i = 0; i < 2; i++) {
            const int f   = tid + i * 256;
            const int row = f >> 2, ch = f & 3;
            const uint32_t so = row * ROWB + ch * 16;
            const size_t ga = (size_t)(bm + row) * K + kof + ch * 8;
            const size_t gb = (size_t)(bn + row) * K + kof + ch * 8;
            cp16(base +            so, Ah + ga);
            cp16(base +     MATB + so, Al + ga);
            cp16(base + 2 * MATB + so, Bh + gb);
            cp16(base + 3 * MATB + so, Bl + gb);
        }
        CP_COMMIT();
    };

    stage(0);
    stage(1);

    const uint32_t a_row  = m0 + (lane & 15);
    const uint32_t a_coff = (uint32_t)((lane >> 4) << 4);
    const uint32_t b_row  = n0 + ((lane >> 4) << 3) + (lane & 7);
    const uint32_t b_coff = (uint32_t)(((lane >> 3) & 1) << 4);

    for (int c = 0; c < nt; c++) {
        if (c + ST - 1 < nt) stage(c + ST - 1);
        else                 CP_COMMIT();
        CP_WAIT1();
        __syncthreads();

        const uint32_t base = sb + (uint32_t)(c % ST) * STAGEB;
        #pragma unroll
        for (int ks = 0; ks < 2; ks++) {
            uint32_t aH[2][4], aL[2][4], bH[8][2], bL[8][2];
            #pragma unroll
            for (int mi = 0; mi < 2; mi++) {
                const uint32_t ra = base + (a_row + mi * 16) * ROWB + ks * 32 + a_coff;
                LDSM4(aH[mi], ra);
                LDSM4(aL[mi], ra + MATB);
            }
            #pragma unroll
            for (int t = 0; t < 4; t++) {
                const uint32_t rb = base + 2 * MATB + (b_row + t * 16) * ROWB + ks * 32 + b_coff;
                uint32_t r[4];
                LDSM4(r, rb);
                bH[2*t][0] = r[0]; bH[2*t][1] = r[1];
                bH[2*t+1][0] = r[2]; bH[2*t+1][1] = r[3];
                LDSM4(r, rb + MATB);
                bL[2*t][0] = r[0]; bL[2*t][1] = r[1];
                bL[2*t+1][0] = r[2]; bL[2*t+1][1] = r[3];
            }
            #pragma unroll
            for (int mi = 0; mi < 2; mi++)
                #pragma unroll
                for (int ni = 0; ni < 8; ni++) {
                    MMA16816(acc[mi][ni], aH[mi], bH[ni]);
                    MMA16816(acc[mi][ni], aL[mi], bH[ni]);
                    MMA16816(acc[mi][ni], aH[mi], bL[ni]);
                }
        }
        __syncthreads();
    }

    #pragma unroll
    for (int mi = 0; mi < 2; mi++) {
        #pragma unroll
        for (int half = 0; half < 2; half++) {
            const int r = bm + m0 + mi * 16 + half * 8 + (lane >> 2);
            const size_t orow = (size_t)r * N;
            #pragma unroll
            for (int ni = 0; ni < 8; ni++) {
                const int cc = bn + n0 + ni * 8 + (lane & 3) * 2;
                float vx = acc[mi][ni][half * 2 + 0];
                float vy = acc[mi][ni][half * 2 + 1];
                const float2 b2 = *(const float2*)(bias + cc);
                vx += b2.x; vy += b2.y;
                if constexpr (RESID) {
                    const float2 rr = *(const float2*)(Rsd + orow + cc);
                    vx += rr.x; vy += rr.y;
                }
                if constexpr (RELU) { vx = fmaxf(vx, 0.f); vy = fmaxf(vy, 0.f); }
                if constexpr (SPLIT) split_store2(Ch + orow + cc, Cl + orow + cc, vx, vy);
                else { float2 o; o.x = vx; o.y = vy; *(float2*)(Cf + orow + cc) = o; }
            }
        }
    }
}

// ================================================================ weight transpose+split
__global__ __launch_bounds__(256)
void tsplit_kernel(const float* __restrict__ W, __nv_bfloat16* __restrict__ Th,
                   __nv_bfloat16* __restrict__ Tl, int K, int N)
{
    __shared__ float t[32][33];
    const int n0 = blockIdx.x * 32, k0 = blockIdx.y * 32;
    const int tx = threadIdx.x, ty = threadIdx.y;
    #pragma unroll
    for (int i = 0; i < 32; i += 8)
        t[ty + i][tx] = W[(size_t)(k0 + ty + i) * N + n0 + tx];
    __syncthreads();
    #pragma unroll
    for (int i = 0; i < 32; i += 8) {
        const float v = t[tx][ty + i];
        const __nv_bfloat16 h = __float2bfloat16(v);
        const __nv_bfloat16 l = __float2bfloat16(v - __bfloat162float(h));
        const size_t o = (size_t)(n0 + ty + i) * K + k0 + tx;
        Th[o] = h; Tl[o] = l;
    }
}

template<bool ADD>
__global__ __launch_bounds__(256)
void split_kernel(const float* __restrict__ a, const float* __restrict__ b,
                  __nv_bfloat16* __restrict__ H, __nv_bfloat16* __restrict__ L)
{
    const size_t i = ((size_t)blockIdx.x * 256 + threadIdx.x) * 4;
    float4 v = *(const float4*)(a + i);
    if constexpr (ADD) {
        const float4 w = *(const float4*)(b + i);
        v.x += w.x; v.y += w.y; v.z += w.z; v.w += w.w;
    }
    split_store4(H + i, L + i, v);
}

// ================================================================ HMMA flash attention
// grid (S/128, B*H), 256 threads (8 warps, m16 each). kv tiles of 64.
// scores = (QhKh + QlKh + QhKl)/8 + corr ; P,V hi/lo 3-term PV. fp32 softmax.
// smem: 2 stages x { Kh,Kl,Vh,Vl : 64 rows x 144B } = 73728 B.
#define AT_STG  36864
#define AT_SMEM (2 * AT_STG)

__global__ __launch_bounds__(256, 1)
void attn_mma(const __nv_bfloat16* __restrict__ Qh, const __nv_bfloat16* __restrict__ Ql,
              const __nv_bfloat16* __restrict__ Kh, const __nv_bfloat16* __restrict__ Kl,
              const __nv_bfloat16* __restrict__ Vh, const __nv_bfloat16* __restrict__ Vl,
              const float* __restrict__ corr,
              __nv_bfloat16* __restrict__ ctx_h, __nv_bfloat16* __restrict__ ctx_l)
{
    extern __shared__ __align__(128) char smem[];
    const uint32_t sb = smem_u32(smem);
    const int tid = threadIdx.x, wid = tid >> 5, lane = tid & 31;
    const int q0 = blockIdx.x * 128;
    const int b  = blockIdx.y >> 4, h = blockIdx.y & 15;
    const size_t tok0 = (size_t)b * 2048;

    // ---- stage Q (hi/lo) into stage0 region, load a-fragments, release ----
    #pragma unroll
    for (int i = 0; i < 4; i++) {
        const int f = tid + i * 256;           // 0..1023
        const int row = f >> 3, ch = f & 7;
        const size_t g = (tok0 + q0 + row) * 1024 + h * 64 + ch * 8;
        cp16(sb +         row * 144 + ch * 16, Qh + g);
        cp16(sb + 18432 + row * 144 + ch * 16, Ql + g);
    }
    CP_COMMIT();
    CP_WAIT0();
    __syncthreads();

    uint32_t qh[4][4], ql[4][4];
    {
        const uint32_t ab = sb + (wid * 16 + (lane & 15)) * 144 + ((lane >> 4) << 4);
        #pragma unroll
        for (int ks = 0; ks < 4; ks++) {
            LDSM4(qh[ks], ab + ks * 32);
            LDSM4(ql[ks], ab + 18432 + ks * 32);
        }
    }
    __syncthreads();

    auto stageKV = [&](int c) {
        const uint32_t base = sb + (uint32_t)(c & 1) * AT_STG;
        const int k0 = c * 64;
        #pragma unroll
        for (int i = 0; i < 8; i++) {
            const int f   = tid + i * 256;     // 0..2047
            const int mat = f >> 9;            // 0..3
            const int idx = f & 511;
            const int row = idx >> 3, ch = idx & 7;
            const size_t g = (tok0 + k0 + row) * 1024 + h * 64 + ch * 8;
            const __nv_bfloat16* src = (mat == 0) ? Kh : (mat == 1) ? Kl : (mat == 2) ? Vh : Vl;
            cp16(base + mat * 9216 + row * 144 + ch * 16, src + g);
        }
        CP_COMMIT();
    };

    float o[8][4];
    #pragma unroll
    for (int d = 0; d < 8; d++)
        #pragma unroll
        for (int q = 0; q < 4; q++) o[d][q] = 0.f;
    float m0 = -1e30f, m1 = -1e30f, l0 = 0.f, l1 = 0.f;

    stageKV(0);

    const uint32_t brow  = ((lane >> 4) << 3) + (lane & 7);
    const uint32_t bcoff = ((lane >> 3) & 1) << 4;
    const int r   = lane >> 2;
    const int cc2 = (lane & 3) * 2;
    const float* corrb = corr + ((size_t)b * 2048 + q0 + wid * 16) * 2048;
    const uint32_t vlrow = ((lane >> 3) & 1) * 8 + (lane & 7);
    const uint32_t vlcol = (uint32_t)((lane >> 4) << 4);   // bytes: (lane>>4)*8 bf16

    for (int c = 0; c < 32; c++) {
        if (c + 1 < 32) stageKV(c + 1);
        else            CP_COMMIT();
        CP_WAIT1();
        __syncthreads();

        const uint32_t kb = sb + (uint32_t)(c & 1) * AT_STG;
        float s[8][4];
        #pragma unroll
        for (int j = 0; j < 8; j++)
            #pragma unroll
            for (int q = 0; q < 4; q++) s[j][q] = 0.f;

        // ---- S = Q K^T (3 terms) ----
        #pragma unroll
        for (int ks = 0; ks < 4; ks++) {
            #pragma unroll
            for (int tp = 0; tp < 4; tp++) {
                uint32_t bh[4], bl[4];
                const uint32_t ad = kb + (brow + tp * 16) * 144 + ks * 32 + bcoff;
                LDSM4(bh, ad);
                LDSM4(bl, ad + 9216);
                MMA16816(s[2*tp],   qh[ks], bh + 0);
                MMA16816(s[2*tp],   ql[ks], bh + 0);
                MMA16816(s[2*tp],   qh[ks], bl + 0);
                MMA16816(s[2*tp+1], qh[ks], bh + 2);
                MMA16816(s[2*tp+1], ql[ks], bh + 2);
                MMA16816(s[2*tp+1], qh[ks], bl + 2);
            }
        }

        // ---- scale + corr ----
        const int k0 = c * 64;
        #pragma unroll
        for (int j = 0; j < 8; j++) {
            const float2 c0 = *(const float2*)(corrb + (size_t)r       * 2048 + k0 + j * 8 + cc2);
            const float2 c1 = *(const float2*)(corrb + (size_t)(r + 8) * 2048 + k0 + j * 8 + cc2);
            s[j][0] = s[j][0] * 0.125f + c0.x;
            s[j][1] = s[j][1] * 0.125f + c0.y;
            s[j][2] = s[j][2] * 0.125f + c1.x;
            s[j][3] = s[j][3] * 0.125f + c1.y;
        }

        // ---- online softmax ----
        float mx0 = s[0][0], mx1 = s[0][2];
        #pragma unroll
        for (int j = 0; j < 8; j++) {
            mx0 = fmaxf(mx0, fmaxf(s[j][0], s[j][1]));
            mx1 = fmaxf(mx1, fmaxf(s[j][2], s[j][3]));
        }
        mx0 = fmaxf(mx0, __shfl_xor_sync(0xffffffffu, mx0, 1));
        mx0 = fmaxf(mx0, __shfl_xor_sync(0xffffffffu, mx0, 2));
        mx1 = fmaxf(mx1, __shfl_xor_sync(0xffffffffu, mx1, 1));
        mx1 = fmaxf(mx1, __shfl_xor_sync(0xffffffffu, mx1, 2));
        const float mn0 = fmaxf(m0, mx0), mn1 = fmaxf(m1, mx1);
        const float sc0 = __expf(m0 - mn0), sc1 = __expf(m1 - mn1);
        float sum0 = 0.f, sum1 = 0.f;
        #pragma unroll
        for (int j = 0; j < 8; j++) {
            s[j][0] = __expf(s[j][0] - mn0);
            s[j][1] = __expf(s[j][1] - mn0);
            s[j][2] = __expf(s[j][2] - mn1);
            s[j][3] = __expf(s[j][3] - mn1);
            sum0 += s[j][0] + s[j][1];
            sum1 += s[j][2] + s[j][3];
        }
        sum0 += __shfl_xor_sync(0xffffffffu, sum0, 1);
        sum0 += __shfl_xor_sync(0xffffffffu, sum0, 2);
        sum1 += __shfl_xor_sync(0xffffffffu, sum1, 1);
        sum1 += __shfl_xor_sync(0xffffffffu, sum1, 2);
        l0 = l0 * sc0 + sum0;
        l1 = l1 * sc1 + sum1;
        m0 = mn0; m1 = mn1;
        #pragma unroll
        for (int d = 0; d < 8; d++) {
            o[d][0] *= sc0; o[d][1] *= sc0;
            o[d][2] *= sc1; o[d][3] *= sc1;
        }

        // ---- O += P V (3 terms: PhVh + PlVh + PhVl) ----
        const uint32_t vb = kb + 18432;
        #pragma unroll
        for (int t = 0; t < 4; t++) {
            uint32_t ah[4], al[4];
            packPS(s[2*t][0],   s[2*t][1],   ah[0], al[0]);
            packPS(s[2*t][2],   s[2*t][3],   ah[1], al[1]);
            packPS(s[2*t+1][0], s[2*t+1][1], ah[2], al[2]);
            packPS(s[2*t+1][2], s[2*t+1][3], ah[3], al[3]);
            #pragma unroll
            for (int dp = 0; dp < 4; dp++) {
                uint32_t bvh[4], bvl[4];
                const uint32_t ad = vb + (t * 16 + vlrow) * 144 + dp * 32 + vlcol;
                LDSM4T(bvh, ad);
                LDSM4T(bvl, ad + 9216);
                MMA16816(o[2*dp],   ah, bvh + 0);
                MMA16816(o[2*dp],   al, bvh + 0);
                MMA16816(o[2*dp],   ah, bvl + 0);
                MMA16816(o[2*dp+1], ah, bvh + 2);
                MMA16816(o[2*dp+1], al, bvh + 2);
                MMA16816(o[2*dp+1], ah, bvl + 2);
            }
        }
        __syncthreads();
    }

    // ---- epilogue ----
    const float i0 = 1.f / l0, i1 = 1.f / l1;
    const size_t row0 = (tok0 + q0 + wid * 16 + r)     * 1024;
    const size_t row1 = (tok0 + q0 + wid * 16 + r + 8) * 1024;
    #pragma unroll
    for (int d = 0; d < 8; d++) {
        const int col = h * 64 + d * 8 + cc2;
        split_store2(ctx_h + row0 + col, ctx_l + row0 + col, o[d][0] * i0, o[d][1] * i0);
        split_store2(ctx_h + row1 + col, ctx_l + row1 + col, o[d][2] * i1, o[d][3] * i1);
    }
}

// ================================================================ LayerNorm
template<bool SPLIT>
__global__ __launch_bounds__(256)
void ln_kernel(const float* __restrict__ in, const float* __restrict__ g,
               const float* __restrict__ b, float* __restrict__ out,
               __nv_bfloat16* __restrict__ H, __nv_bfloat16* __restrict__ L)
{
    __shared__ float rs[8], rq[8];
    const int tid = threadIdx.x;
    const size_t base = (size_t)blockIdx.x * 1024;

    const float4 v = *(const float4*)(in + base + tid * 4);
    float s  = v.x + v.y + v.z + v.w;
    float q2 = v.x*v.x + v.y*v.y + v.z*v.z + v.w*v.w;
    #pragma unroll
    for (int o = 16; o > 0; o >>= 1) {
        s  += __shfl_xor_sync(0xffffffffu, s,  o);
        q2 += __shfl_xor_sync(0xffffffffu, q2, o);
    }
    if ((tid & 31) == 0) { rs[tid >> 5] = s; rq[tid >> 5] = q2; }
    __syncthreads();
    float ts = 0.f, tq = 0.f;
    #pragma unroll
    for (int w = 0; w < 8; w++) { ts += rs[w]; tq += rq[w]; }

    const float mu   = ts * (1.f / 1024.f);
    const float var  = tq * (1.f / 1024.f) - mu * mu;
    const float invs = rsqrtf(var + 1e-5f);

    const float4 gg = *(const float4*)(g + tid * 4);
    const float4 bb = *(const float4*)(b + tid * 4);
    float4 o;
    o.x = (v.x - mu) * invs * gg.x + bb.x;
    o.y = (v.y - mu) * invs * gg.y + bb.y;
    o.z = (v.z - mu) * invs * gg.z + bb.z;
    o.w = (v.w - mu) * invs * gg.w + bb.w;
    *(float4*)(out + base + tid * 4) = o;
    if constexpr (SPLIT) split_store4(H + base + tid * 4, L + base + tid * 4, o);
}

// ================================================================ launch
extern "C" void kernel_launch(void* const* d_in, const int* in_sizes, int n_in,
                              void* d_out, int out_size)
{
    (void)in_sizes; (void)n_in; (void)out_size;
    const float* src  = (const float*)d_in[0];
    const float* corr = (const float*)d_in[1];
    const float* pos  = (const float*)d_in[2];
    const float* Wq   = (const float*)d_in[3];
    const float* bq   = (const float*)d_in[4];
    const float* Wk   = (const float*)d_in[5];
    const float* bk   = (const float*)d_in[6];
    const float* Wv   = (const float*)d_in[7];
    const float* bv   = (const float*)d_in[8];
    const float* Wo   = (const float*)d_in[9];
    const float* bo   = (const float*)d_in[10];
    const float* W1   = (const float*)d_in[11];
    const float* b1   = (const float*)d_in[12];
    const float* W2   = (const float*)d_in[13];
    const float* b2   = (const float*)d_in[14];
    const float* g1   = (const float*)d_in[15];
    const float* be1  = (const float*)d_in[16];
    const float* g2   = (const float*)d_in[17];
    const float* be2  = (const float*)d_in[18];
    float* out = (float*)d_out;

    float *y, *x, *y2;
    __nv_bfloat16 *qkh, *qkl, *sh, *sl, *cth, *ctl, *xh, *xl, *ffh, *ffl, *wth, *wtl;
    __nv_bfloat16 *qbh, *qbl, *kbh, *kbl, *vbh, *vbl;
    cudaGetSymbolAddress((void**)&y,   g_y);      cudaGetSymbolAddress((void**)&x,   g_x);
    cudaGetSymbolAddress((void**)&y2,  g_y2);
    cudaGetSymbolAddress((void**)&qkh, g_qkin_h); cudaGetSymbolAddress((void**)&qkl, g_qkin_l);
    cudaGetSymbolAddress((void**)&sh,  g_src_h);  cudaGetSymbolAddress((void**)&sl,  g_src_l);
    cudaGetSymbolAddress((void**)&qbh, g_qb_h);   cudaGetSymbolAddress((void**)&qbl, g_qb_l);
    cudaGetSymbolAddress((void**)&kbh, g_kb_h);   cudaGetSymbolAddress((void**)&kbl, g_kb_l);
    cudaGetSymbolAddress((void**)&vbh, g_vb_h);   cudaGetSymbolAddress((void**)&vbl, g_vb_l);
    cudaGetSymbolAddress((void**)&cth, g_ctx_h);  cudaGetSymbolAddress((void**)&ctl, g_ctx_l);
    cudaGetSymbolAddress((void**)&xh,  g_x_h);    cudaGetSymbolAddress((void**)&xl,  g_x_l);
    cudaGetSymbolAddress((void**)&ffh, g_ff_h);   cudaGetSymbolAddress((void**)&ffl, g_ff_l);
    cudaGetSymbolAddress((void**)&wth, g_wt_h);   cudaGetSymbolAddress((void**)&wtl, g_wt_l);

    const size_t OQ = 0, OK_ = 1u<<20, OV = 2u<<20, OO = 3u<<20, O1 = 4u<<20, O2 = 8u<<20;

    cudaFuncSetAttribute(gemm_tc<false,false,true >, cudaFuncAttributeMaxDynamicSharedMemorySize, GEMM_SMEM);
    cudaFuncSetAttribute(gemm_tc<false,true ,false>, cudaFuncAttributeMaxDynamicSharedMemorySize, GEMM_SMEM);
    cudaFuncSetAttribute(gemm_tc<true ,false,true >, cudaFuncAttributeMaxDynamicSharedMemorySize, GEMM_SMEM);
    cudaFuncSetAttribute(attn_mma, cudaFuncAttributeMaxDynamicSharedMemorySize, AT_SMEM);

    const dim3 tb(32, 8);
    tsplit_kernel<<<dim3(1024/32, 1024/32), tb>>>(Wq, wth + OQ,  wtl + OQ,  1024, 1024);
    tsplit_kernel<<<dim3(1024/32, 1024/32), tb>>>(Wk, wth + OK_, wtl + OK_, 1024, 1024);
    tsplit_kernel<<<dim3(1024/32, 1024/32), tb>>>(Wv, wth + OV,  wtl + OV,  1024, 1024);
    tsplit_kernel<<<dim3(1024/32, 1024/32), tb>>>(Wo, wth + OO,  wtl + OO,  1024, 1024);
    tsplit_kernel<<<dim3(4096/32, 1024/32), tb>>>(W1, wth + O1,  wtl + O1,  1024, 4096);
    tsplit_kernel<<<dim3(1024/32, 4096/32), tb>>>(W2, wth + O2,  wtl + O2,  4096, 1024);

    split_kernel<true ><<<4096, 256>>>(src, pos,     qkh, qkl);
    split_kernel<false><<<4096, 256>>>(src, nullptr, sh,  sl);

    const dim3 gP(8, 32), gF1(32, 32);
    // projections -> bf16 hi/lo q,k,v
    gemm_tc<false,false,true ><<<gP, 256, GEMM_SMEM>>>(qkh, qkl, wth + OQ,  wtl + OQ,  bq, nullptr, nullptr, qbh, qbl, 4096, 1024, 1024);
    gemm_tc<false,false,true ><<<gP, 256, GEMM_SMEM>>>(qkh, qkl, wth + OK_, wtl + OK_, bk, nullptr, nullptr, kbh, kbl, 4096, 1024, 1024);
    gemm_tc<false,false,true ><<<gP, 256, GEMM_SMEM>>>(sh,  sl,  wth + OV,  wtl + OV,  bv, nullptr, nullptr, vbh, vbl, 4096, 1024, 1024);

    attn_mma<<<dim3(16, 32), 256, AT_SMEM>>>(qbh, qbl, kbh, kbl, vbh, vbl, corr, cth, ctl);

    gemm_tc<false,true ,false><<<gP, 256, GEMM_SMEM>>>(cth, ctl, wth + OO, wtl + OO, bo, src, y, nullptr, nullptr, 4096, 1024, 1024);
    ln_kernel<true ><<<4096, 256>>>(y, g1, be1, x, xh, xl);

    gemm_tc<true ,false,true ><<<gF1, 256, GEMM_SMEM>>>(xh,  xl,  wth + O1, wtl + O1, b1, nullptr, nullptr, ffh, ffl, 4096, 4096, 1024);
    gemm_tc<false,true ,false><<<gP,  256, GEMM_SMEM>>>(ffh, ffl, wth + O2, wtl + O2, b2, x,       y2, nullptr, nullptr, 4096, 1024, 4096);
    ln_kernel<false><<<4096, 256>>>(y2, g2, be2, out, nullptr, nullptr);
}

// round 11
// speedup vs baseline: 1.6618x; 1.0002x over previous
#include <cuda_runtime.h>
#include <cuda_bf16.h>
#include <math.h>
#include <stdint.h>

// B=2, S=2048, D_MODEL=1024, HEADS=16, D_K=64, D_FF=4096, tokens M=4096

// ---------------------------------------------------------------- scratch
__device__ __align__(128) float g_y [1u<<22];
__device__ __align__(128) float g_x [1u<<22];
__device__ __align__(128) float g_y2[1u<<22];
__device__ __align__(128) __nv_bfloat16 g_qkin_h[1u<<22], g_qkin_l[1u<<22];
__device__ __align__(128) __nv_bfloat16 g_src_h [1u<<22], g_src_l [1u<<22];
__device__ __align__(128) __nv_bfloat16 g_qb_h  [1u<<22], g_qb_l  [1u<<22];
__device__ __align__(128) __nv_bfloat16 g_kb_h  [1u<<22], g_kb_l  [1u<<22];
__device__ __align__(128) __nv_bfloat16 g_vb_h  [1u<<22], g_vb_l  [1u<<22];
__device__ __align__(128) __nv_bfloat16 g_ctx_h [1u<<22], g_ctx_l [1u<<22];
__device__ __align__(128) __nv_bfloat16 g_x_h   [1u<<22], g_x_l   [1u<<22];
__device__ __align__(128) __nv_bfloat16 g_ff_h  [1u<<24], g_ff_l  [1u<<24];
__device__ __align__(128) __nv_bfloat16 g_wt_h  [12u<<20], g_wt_l [12u<<20];

// ---------------------------------------------------------------- helpers
__device__ __forceinline__ uint32_t smem_u32(const void* p) {
    uint32_t a;
    asm("{ .reg .u64 t; cvta.to.shared.u64 t, %1; cvt.u32.u64 %0, t; }" : "=r"(a) : "l"(p));
    return a;
}
__device__ __forceinline__ void cp16(uint32_t dst, const void* src) {
    asm volatile("cp.async.cg.shared.global [%0], [%1], 16;"
                 :: "r"(dst), "l"(__cvta_generic_to_global(src)) : "memory");
}
#define CP_COMMIT() asm volatile("cp.async.commit_group;" ::: "memory")
#define CP_WAIT1()  asm volatile("cp.async.wait_group 1;"  ::: "memory")
#define CP_WAIT0()  asm volatile("cp.async.wait_group 0;"  ::: "memory")

#define LDSM4(r, addr) \
    asm volatile("ldmatrix.sync.aligned.m8n8.x4.shared.b16 {%0,%1,%2,%3}, [%4];" \
                 : "=r"((r)[0]), "=r"((r)[1]), "=r"((r)[2]), "=r"((r)[3]) : "r"(addr))
#define LDSM4T(r, addr) \
    asm volatile("ldmatrix.sync.aligned.m8n8.x4.trans.shared.b16 {%0,%1,%2,%3}, [%4];" \
                 : "=r"((r)[0]), "=r"((r)[1]), "=r"((r)[2]), "=r"((r)[3]) : "r"(addr))

#define MMA16816(d, a, b) \
    asm volatile("mma.sync.aligned.m16n8k16.row.col.f32.bf16.bf16.f32 " \
                 "{%0,%1,%2,%3}, {%4,%5,%6,%7}, {%8,%9}, {%0,%1,%2,%3};" \
                 : "+f"((d)[0]), "+f"((d)[1]), "+f"((d)[2]), "+f"((d)[3]) \
                 : "r"((a)[0]), "r"((a)[1]), "r"((a)[2]), "r"((a)[3]), \
                   "r"((b)[0]), "r"((b)[1]))

__device__ __forceinline__ void split_store4(__nv_bfloat16* __restrict__ H,
                                             __nv_bfloat16* __restrict__ L, float4 v) {
    union { __nv_bfloat16 b[4]; uint2 u; } hv, lv;
    hv.b[0] = __float2bfloat16(v.x); lv.b[0] = __float2bfloat16(v.x - __bfloat162float(hv.b[0]));
    hv.b[1] = __float2bfloat16(v.y); lv.b[1] = __float2bfloat16(v.y - __bfloat162float(hv.b[1]));
    hv.b[2] = __float2bfloat16(v.z); lv.b[2] = __float2bfloat16(v.z - __bfloat162float(hv.b[2]));
    hv.b[3] = __float2bfloat16(v.w); lv.b[3] = __float2bfloat16(v.w - __bfloat162float(hv.b[3]));
    *(uint2*)H = hv.u;
    *(uint2*)L = lv.u;
}
__device__ __forceinline__ void split_store2(__nv_bfloat16* __restrict__ H,
                                             __nv_bfloat16* __restrict__ L,
                                             float x, float y) {
    union { __nv_bfloat16 b[2]; uint32_t u; } hv, lv;
    hv.b[0] = __float2bfloat16(x); lv.b[0] = __float2bfloat16(x - __bfloat162float(hv.b[0]));
    hv.b[1] = __float2bfloat16(y); lv.b[1] = __float2bfloat16(y - __bfloat162float(hv.b[1]));
    *(uint32_t*)H = hv.u;
    *(uint32_t*)L = lv.u;
}
// pack (x lo, y hi) to bf16x2 + residual pair
__device__ __forceinline__ void packPS(float x, float y, uint32_t& ph, uint32_t& pl) {
    asm("cvt.rn.bf16x2.f32 %0, %1, %2;" : "=r"(ph) : "f"(y), "f"(x));
    const float rx = x - __uint_as_float(ph << 16);
    const float ry = y - __uint_as_float(ph & 0xffff0000u);
    asm("cvt.rn.bf16x2.f32 %0, %1, %2;" : "=r"(pl) : "f"(ry), "f"(rx));
}

// ================================================================ HMMA GEMM
#define ST      3
#define CHUNK   32
#define ROWB    80
#define MATB    (128 * ROWB)
#define STAGEB  (4 * MATB)
#define GEMM_SMEM (ST * STAGEB)

template<bool RELU, bool RESID, bool SPLIT>
__global__ __launch_bounds__(256, 1)
void gemm_tc(const __nv_bfloat16* __restrict__ Ah, const __nv_bfloat16* __restrict__ Al,
             const __nv_bfloat16* __restrict__ Bh, const __nv_bfloat16* __restrict__ Bl,
             const float* __restrict__ bias, const float* __restrict__ Rsd,
             float* __restrict__ Cf, __nv_bfloat16* __restrict__ Ch, __nv_bfloat16* __restrict__ Cl,
             int M, int N, int K)
{
    extern __shared__ __align__(128) char smem[];
    const uint32_t sb = smem_u32(smem);
    const int tid  = threadIdx.x;
    const int wid  = tid >> 5, lane = tid & 31;
    const int bm   = blockIdx.y * 128, bn = blockIdx.x * 128;
    const int m0   = (wid & 3) * 32;
    const int n0   = (wid >> 2) * 64;
    const int nt   = K / CHUNK;

    float acc[2][8][4];
    #pragma unroll
    for (int i = 0; i < 2; i++)
        #pragma unroll
        for (int j = 0; j < 8; j++)
            #pragma unroll
            for (int q = 0; q < 4; q++) acc[i][j][q] = 0.f;

    auto stage = [&](int c) {
        const uint32_t base = sb + (uint32_t)(c % ST) * STAGEB;
        const size_t kof = (size_t)c * CHUNK;
        #pragma unroll
        for (int i = 0; i < 2; i++) {
            const int f   = tid + i * 256;
            const int row = f >> 2, ch = f & 3;
            const uint32_t so = row * ROWB + ch * 16;
            const size_t ga = (size_t)(bm + row) * K + kof + ch * 8;
            const size_t gb = (size_t)(bn + row) * K + kof + ch * 8;
            cp16(base +            so, Ah + ga);
            cp16(base +     MATB + so, Al + ga);
            cp16(base + 2 * MATB + so, Bh + gb);
            cp16(base + 3 * MATB + so, Bl + gb);
        }
        CP_COMMIT();
    };

    stage(0);
    stage(1);

    const uint32_t a_row  = m0 + (lane & 15);
    const uint32_t a_coff = (uint32_t)((lane >> 4) << 4);
    const uint32_t b_row  = n0 + ((lane >> 4) << 3) + (lane & 7);
    const uint32_t b_coff = (uint32_t)(((lane >> 3) & 1) << 4);

    for (int c = 0; c < nt; c++) {
        if (c + ST - 1 < nt) stage(c + ST - 1);
        else                 CP_COMMIT();
        CP_WAIT1();
        __syncthreads();

        const uint32_t base = sb + (uint32_t)(c % ST) * STAGEB;
        #pragma unroll
        for (int ks = 0; ks < 2; ks++) {
            uint32_t aH[2][4], aL[2][4], bH[8][2], bL[8][2];
            #pragma unroll
            for (int mi = 0; mi < 2; mi++) {
                const uint32_t ra = base + (a_row + mi * 16) * ROWB + ks * 32 + a_coff;
                LDSM4(aH[mi], ra);
                LDSM4(aL[mi], ra + MATB);
            }
            #pragma unroll
            for (int t = 0; t < 4; t++) {
                const uint32_t rb = base + 2 * MATB + (b_row + t * 16) * ROWB + ks * 32 + b_coff;
                uint32_t r[4];
                LDSM4(r, rb);
                bH[2*t][0] = r[0]; bH[2*t][1] = r[1];
                bH[2*t+1][0] = r[2]; bH[2*t+1][1] = r[3];
                LDSM4(r, rb + MATB);
                bL[2*t][0] = r[0]; bL[2*t][1] = r[1];
                bL[2*t+1][0] = r[2]; bL[2*t+1][1] = r[3];
            }
            #pragma unroll
            for (int mi = 0; mi < 2; mi++)
                #pragma unroll
                for (int ni = 0; ni < 8; ni++) {
                    MMA16816(acc[mi][ni], aH[mi], bH[ni]);
                    MMA16816(acc[mi][ni], aL[mi], bH[ni]);
                    MMA16816(acc[mi][ni], aH[mi], bL[ni]);
                }
        }
        __syncthreads();
    }

    #pragma unroll
    for (int mi = 0; mi < 2; mi++) {
        #pragma unroll
        for (int half = 0; half < 2; half++) {
            const int r = bm + m0 + mi * 16 + half * 8 + (lane >> 2);
            const size_t orow = (size_t)r * N;
            #pragma unroll
            for (int ni = 0; ni < 8; ni++) {
                const int cc = bn + n0 + ni * 8 + (lane & 3) * 2;
                float vx = acc[mi][ni][half * 2 + 0];
                float vy = acc[mi][ni][half * 2 + 1];
                const float2 b2 = *(const float2*)(bias + cc);
                vx += b2.x; vy += b2.y;
                if constexpr (RESID) {
                    const float2 rr = *(const float2*)(Rsd + orow + cc);
                    vx += rr.x; vy += rr.y;
                }
                if constexpr (RELU) { vx = fmaxf(vx, 0.f); vy = fmaxf(vy, 0.f); }
                if constexpr (SPLIT) split_store2(Ch + orow + cc, Cl + orow + cc, vx, vy);
                else { float2 o; o.x = vx; o.y = vy; *(float2*)(Cf + orow + cc) = o; }
            }
        }
    }
}

// ================================================================ weight transpose+split
__global__ __launch_bounds__(256)
void tsplit_kernel(const float* __restrict__ W, __nv_bfloat16* __restrict__ Th,
                   __nv_bfloat16* __restrict__ Tl, int K, int N)
{
    __shared__ float t[32][33];
    const int n0 = blockIdx.x * 32, k0 = blockIdx.y * 32;
    const int tx = threadIdx.x, ty = threadIdx.y;
    #pragma unroll
    for (int i = 0; i < 32; i += 8)
        t[ty + i][tx] = W[(size_t)(k0 + ty + i) * N + n0 + tx];
    __syncthreads();
    #pragma unroll
    for (int i = 0; i < 32; i += 8) {
        const float v = t[tx][ty + i];
        const __nv_bfloat16 h = __float2bfloat16(v);
        const __nv_bfloat16 l = __float2bfloat16(v - __bfloat162float(h));
        const size_t o = (size_t)(n0 + ty + i) * K + k0 + tx;
        Th[o] = h; Tl[o] = l;
    }
}

template<bool ADD>
__global__ __launch_bounds__(256)
void split_kernel(const float* __restrict__ a, const float* __restrict__ b,
                  __nv_bfloat16* __restrict__ H, __nv_bfloat16* __restrict__ L)
{
    const size_t i = ((size_t)blockIdx.x * 256 + threadIdx.x) * 4;
    float4 v = *(const float4*)(a + i);
    if constexpr (ADD) {
        const float4 w = *(const float4*)(b + i);
        v.x += w.x; v.y += w.y; v.z += w.z; v.w += w.w;
    }
    split_store4(H + i, L + i, v);
}

// ================================================================ HMMA flash attention
// grid (S/128, B*H), 256 threads (8 warps, m16 each). kv tiles of 64.
// scores = (QhKh + QlKh + QhKl)/8 + corr ; P,V hi/lo 3-term PV. fp32 softmax.
// smem: 2 stages x { Kh,Kl,Vh,Vl : 64 rows x 144B } = 73728 B.
#define AT_STG  36864
#define AT_SMEM (2 * AT_STG)

__global__ __launch_bounds__(256, 1)
void attn_mma(const __nv_bfloat16* __restrict__ Qh, const __nv_bfloat16* __restrict__ Ql,
              const __nv_bfloat16* __restrict__ Kh, const __nv_bfloat16* __restrict__ Kl,
              const __nv_bfloat16* __restrict__ Vh, const __nv_bfloat16* __restrict__ Vl,
              const float* __restrict__ corr,
              __nv_bfloat16* __restrict__ ctx_h, __nv_bfloat16* __restrict__ ctx_l)
{
    extern __shared__ __align__(128) char smem[];
    const uint32_t sb = smem_u32(smem);
    const int tid = threadIdx.x, wid = tid >> 5, lane = tid & 31;
    const int q0 = blockIdx.x * 128;
    const int b  = blockIdx.y >> 4, h = blockIdx.y & 15;
    const size_t tok0 = (size_t)b * 2048;

    // ---- stage Q (hi/lo) into stage0 region, load a-fragments, release ----
    #pragma unroll
    for (int i = 0; i < 4; i++) {
        const int f = tid + i * 256;           // 0..1023
        const int row = f >> 3, ch = f & 7;
        const size_t g = (tok0 + q0 + row) * 1024 + h * 64 + ch * 8;
        cp16(sb +         row * 144 + ch * 16, Qh + g);
        cp16(sb + 18432 + row * 144 + ch * 16, Ql + g);
    }
    CP_COMMIT();
    CP_WAIT0();
    __syncthreads();

    uint32_t qh[4][4], ql[4][4];
    {
        const uint32_t ab = sb + (wid * 16 + (lane & 15)) * 144 + ((lane >> 4) << 4);
        #pragma unroll
        for (int ks = 0; ks < 4; ks++) {
            LDSM4(qh[ks], ab + ks * 32);
            LDSM4(ql[ks], ab + 18432 + ks * 32);
        }
    }
    __syncthreads();

    auto stageKV = [&](int c) {
        const uint32_t base = sb + (uint32_t)(c & 1) * AT_STG;
        const int k0 = c * 64;
        #pragma unroll
        for (int i = 0; i < 8; i++) {
            const int f   = tid + i * 256;     // 0..2047
            const int mat = f >> 9;            // 0..3
            const int idx = f & 511;
            const int row = idx >> 3, ch = idx & 7;
            const size_t g = (tok0 + k0 + row) * 1024 + h * 64 + ch * 8;
            const __nv_bfloat16* src = (mat == 0) ? Kh : (mat == 1) ? Kl : (mat == 2) ? Vh : Vl;
            cp16(base + mat * 9216 + row * 144 + ch * 16, src + g);
        }
        CP_COMMIT();
    };

    float o[8][4];
    #pragma unroll
    for (int d = 0; d < 8; d++)
        #pragma unroll
        for (int q = 0; q < 4; q++) o[d][q] = 0.f;
    float m0 = -1e30f, m1 = -1e30f, l0 = 0.f, l1 = 0.f;

    stageKV(0);

    const uint32_t brow  = ((lane >> 4) << 3) + (lane & 7);
    const uint32_t bcoff = ((lane >> 3) & 1) << 4;
    const int r   = lane >> 2;
    const int cc2 = (lane & 3) * 2;
    const float* corrb = corr + ((size_t)b * 2048 + q0 + wid * 16) * 2048;
    const uint32_t vlrow = ((lane >> 3) & 1) * 8 + (lane & 7);
    const uint32_t vlcol = (uint32_t)((lane >> 4) << 4);   // bytes: (lane>>4)*8 bf16

    for (int c = 0; c < 32; c++) {
        if (c + 1 < 32) stageKV(c + 1);
        else            CP_COMMIT();
        CP_WAIT1();
        __syncthreads();

        const uint32_t kb = sb + (uint32_t)(c & 1) * AT_STG;
        float s[8][4];
        #pragma unroll
        for (int j = 0; j < 8; j++)
            #pragma unroll
            for (int q = 0; q < 4; q++) s[j][q] = 0.f;

        // ---- S = Q K^T (3 terms) ----
        #pragma unroll
        for (int ks = 0; ks < 4; ks++) {
            #pragma unroll
            for (int tp = 0; tp < 4; tp++) {
                uint32_t bh[4], bl[4];
                const uint32_t ad = kb + (brow + tp * 16) * 144 + ks * 32 + bcoff;
                LDSM4(bh, ad);
                LDSM4(bl, ad + 9216);
                MMA16816(s[2*tp],   qh[ks], bh + 0);
                MMA16816(s[2*tp],   ql[ks], bh + 0);
                MMA16816(s[2*tp],   qh[ks], bl + 0);
                MMA16816(s[2*tp+1], qh[ks], bh + 2);
                MMA16816(s[2*tp+1], ql[ks], bh + 2);
                MMA16816(s[2*tp+1], qh[ks], bl + 2);
            }
        }

        // ---- scale + corr ----
        const int k0 = c * 64;
        #pragma unroll
        for (int j = 0; j < 8; j++) {
            const float2 c0 = *(const float2*)(corrb + (size_t)r       * 2048 + k0 + j * 8 + cc2);
            const float2 c1 = *(const float2*)(corrb + (size_t)(r + 8) * 2048 + k0 + j * 8 + cc2);
            s[j][0] = s[j][0] * 0.125f + c0.x;
            s[j][1] = s[j][1] * 0.125f + c0.y;
            s[j][2] = s[j][2] * 0.125f + c1.x;
            s[j][3] = s[j][3] * 0.125f + c1.y;
        }

        // ---- online softmax ----
        float mx0 = s[0][0], mx1 = s[0][2];
        #pragma unroll
        for (int j = 0; j < 8; j++) {
            mx0 = fmaxf(mx0, fmaxf(s[j][0], s[j][1]));
            mx1 = fmaxf(mx1, fmaxf(s[j][2], s[j][3]));
        }
        mx0 = fmaxf(mx0, __shfl_xor_sync(0xffffffffu, mx0, 1));
        mx0 = fmaxf(mx0, __shfl_xor_sync(0xffffffffu, mx0, 2));
        mx1 = fmaxf(mx1, __shfl_xor_sync(0xffffffffu, mx1, 1));
        mx1 = fmaxf(mx1, __shfl_xor_sync(0xffffffffu, mx1, 2));
        const float mn0 = fmaxf(m0, mx0), mn1 = fmaxf(m1, mx1);
        const float sc0 = __expf(m0 - mn0), sc1 = __expf(m1 - mn1);
        float sum0 = 0.f, sum1 = 0.f;
        #pragma unroll
        for (int j = 0; j < 8; j++) {
            s[j][0] = __expf(s[j][0] - mn0);
            s[j][1] = __expf(s[j][1] - mn0);
            s[j][2] = __expf(s[j][2] - mn1);
            s[j][3] = __expf(s[j][3] - mn1);
            sum0 += s[j][0] + s[j][1];
            sum1 += s[j][2] + s[j][3];
        }
        sum0 += __shfl_xor_sync(0xffffffffu, sum0, 1);
        sum0 += __shfl_xor_sync(0xffffffffu, sum0, 2);
        sum1 += __shfl_xor_sync(0xffffffffu, sum1, 1);
        sum1 += __shfl_xor_sync(0xffffffffu, sum1, 2);
        l0 = l0 * sc0 + sum0;
        l1 = l1 * sc1 + sum1;
        m0 = mn0; m1 = mn1;
        #pragma unroll
        for (int d = 0; d < 8; d++) {
            o[d][0] *= sc0; o[d][1] *= sc0;
            o[d][2] *= sc1; o[d][3] *= sc1;
        }

        // ---- O += P V (3 terms: PhVh + PlVh + PhVl) ----
        const uint32_t vb = kb + 18432;
        #pragma unroll
        for (int t = 0; t < 4; t++) {
            uint32_t ah[4], al[4];
            packPS(s[2*t][0],   s[2*t][1],   ah[0], al[0]);
            packPS(s[2*t][2],   s[2*t][3],   ah[1], al[1]);
            packPS(s[2*t+1][0], s[2*t+1][1], ah[2], al[2]);
            packPS(s[2*t+1][2], s[2*t+1][3], ah[3], al[3]);
            #pragma unroll
            for (int dp = 0; dp < 4; dp++) {
                uint32_t bvh[4], bvl[4];
                const uint32_t ad = vb + (t * 16 + vlrow) * 144 + dp * 32 + vlcol;
                LDSM4T(bvh, ad);
                LDSM4T(bvl, ad + 9216);
                MMA16816(o[2*dp],   ah, bvh + 0);
                MMA16816(o[2*dp],   al, bvh + 0);
                MMA16816(o[2*dp],   ah, bvl + 0);
                MMA16816(o[2*dp+1], ah, bvh + 2);
                MMA16816(o[2*dp+1], al, bvh + 2);
                MMA16816(o[2*dp+1], ah, bvl + 2);
            }
        }
        __syncthreads();
    }

    // ---- epilogue ----
    const float i0 = 1.f / l0, i1 = 1.f / l1;
    const size_t row0 = (tok0 + q0 + wid * 16 + r)     * 1024;
    const size_t row1 = (tok0 + q0 + wid * 16 + r + 8) * 1024;
    #pragma unroll
    for (int d = 0; d < 8; d++) {
        const int col = h * 64 + d * 8 + cc2;
        split_store2(ctx_h + row0 + col, ctx_l + row0 + col, o[d][0] * i0, o[d][1] * i0);
        split_store2(ctx_h + row1 + col, ctx_l + row1 + col, o[d][2] * i1, o[d][3] * i1);
    }
}

// ================================================================ LayerNorm
template<bool SPLIT>
__global__ __launch_bounds__(256)
void ln_kernel(const float* __restrict__ in, const float* __restrict__ g,
               const float* __restrict__ b, float* __restrict__ out,
               __nv_bfloat16* __restrict__ H, __nv_bfloat16* __restrict__ L)
{
    __shared__ float rs[8], rq[8];
    const int tid = threadIdx.x;
    const size_t base = (size_t)blockIdx.x * 1024;

    const float4 v = *(const float4*)(in + base + tid * 4);
    float s  = v.x + v.y + v.z + v.w;
    float q2 = v.x*v.x + v.y*v.y + v.z*v.z + v.w*v.w;
    #pragma unroll
    for (int o = 16; o > 0; o >>= 1) {
        s  += __shfl_xor_sync(0xffffffffu, s,  o);
        q2 += __shfl_xor_sync(0xffffffffu, q2, o);
    }
    if ((tid & 31) == 0) { rs[tid >> 5] = s; rq[tid >> 5] = q2; }
    __syncthreads();
    float ts = 0.f, tq = 0.f;
    #pragma unroll
    for (int w = 0; w < 8; w++) { ts += rs[w]; tq += rq[w]; }

    const float mu   = ts * (1.f / 1024.f);
    const float var  = tq * (1.f / 1024.f) - mu * mu;
    const float invs = rsqrtf(var + 1e-5f);

    const float4 gg = *(const float4*)(g + tid * 4);
    const float4 bb = *(const float4*)(b + tid * 4);
    float4 o;
    o.x = (v.x - mu) * invs * gg.x + bb.x;
    o.y = (v.y - mu) * invs * gg.y + bb.y;
    o.z = (v.z - mu) * invs * gg.z + bb.z;
    o.w = (v.w - mu) * invs * gg.w + bb.w;
    *(float4*)(out + base + tid * 4) = o;
    if constexpr (SPLIT) split_store4(H + base + tid * 4, L + base + tid * 4, o);
}

// ================================================================ launch
extern "C" void kernel_launch(void* const* d_in, const int* in_sizes, int n_in,
                              void* d_out, int out_size)
{
    (void)in_sizes; (void)n_in; (void)out_size;
    const float* src  = (const float*)d_in[0];
    const float* corr = (const float*)d_in[1];
    const float* pos  = (const float*)d_in[2];
    const float* Wq   = (const float*)d_in[3];
    const float* bq   = (const float*)d_in[4];
    const float* Wk   = (const float*)d_in[5];
    const float* bk   = (const float*)d_in[6];
    const float* Wv   = (const float*)d_in[7];
    const float* bv   = (const float*)d_in[8];
    const float* Wo   = (const float*)d_in[9];
    const float* bo   = (const float*)d_in[10];
    const float* W1   = (const float*)d_in[11];
    const float* b1   = (const float*)d_in[12];
    const float* W2   = (const float*)d_in[13];
    const float* b2   = (const float*)d_in[14];
    const float* g1   = (const float*)d_in[15];
    const float* be1  = (const float*)d_in[16];
    const float* g2   = (const float*)d_in[17];
    const float* be2  = (const float*)d_in[18];
    float* out = (float*)d_out;

    float *y, *x, *y2;
    __nv_bfloat16 *qkh, *qkl, *sh, *sl, *cth, *ctl, *xh, *xl, *ffh, *ffl, *wth, *wtl;
    __nv_bfloat16 *qbh, *qbl, *kbh, *kbl, *vbh, *vbl;
    cudaGetSymbolAddress((void**)&y,   g_y);      cudaGetSymbolAddress((void**)&x,   g_x);
    cudaGetSymbolAddress((void**)&y2,  g_y2);
    cudaGetSymbolAddress((void**)&qkh, g_qkin_h); cudaGetSymbolAddress((void**)&qkl, g_qkin_l);
    cudaGetSymbolAddress((void**)&sh,  g_src_h);  cudaGetSymbolAddress((void**)&sl,  g_src_l);
    cudaGetSymbolAddress((void**)&qbh, g_qb_h);   cudaGetSymbolAddress((void**)&qbl, g_qb_l);
    cudaGetSymbolAddress((void**)&kbh, g_kb_h);   cudaGetSymbolAddress((void**)&kbl, g_kb_l);
    cudaGetSymbolAddress((void**)&vbh, g_vb_h);   cudaGetSymbolAddress((void**)&vbl, g_vb_l);
    cudaGetSymbolAddress((void**)&cth, g_ctx_h);  cudaGetSymbolAddress((void**)&ctl, g_ctx_l);
    cudaGetSymbolAddress((void**)&xh,  g_x_h);    cudaGetSymbolAddress((void**)&xl,  g_x_l);
    cudaGetSymbolAddress((void**)&ffh, g_ff_h);   cudaGetSymbolAddress((void**)&ffl, g_ff_l);
    cudaGetSymbolAddress((void**)&wth, g_wt_h);   cudaGetSymbolAddress((void**)&wtl, g_wt_l);

    const size_t OQ = 0, OK_ = 1u<<20, OV = 2u<<20, OO = 3u<<20, O1 = 4u<<20, O2 = 8u<<20;

    cudaFuncSetAttribute(gemm_tc<false,false,true >, cudaFuncAttributeMaxDynamicSharedMemorySize, GEMM_SMEM);
    cudaFuncSetAttribute(gemm_tc<false,true ,false>, cudaFuncAttributeMaxDynamicSharedMemorySize, GEMM_SMEM);
    cudaFuncSetAttribute(gemm_tc<true ,false,true >, cudaFuncAttributeMaxDynamicSharedMemorySize, GEMM_SMEM);
    cudaFuncSetAttribute(attn_mma, cudaFuncAttributeMaxDynamicSharedMemorySize, AT_SMEM);

    const dim3 tb(32, 8);
    tsplit_kernel<<<dim3(1024/32, 1024/32), tb>>>(Wq, wth + OQ,  wtl + OQ,  1024, 1024);
    tsplit_kernel<<<dim3(1024/32, 1024/32), tb>>>(Wk, wth + OK_, wtl + OK_, 1024, 1024);
    tsplit_kernel<<<dim3(1024/32, 1024/32), tb>>>(Wv, wth + OV,  wtl + OV,  1024, 1024);
    tsplit_kernel<<<dim3(1024/32, 1024/32), tb>>>(Wo, wth + OO,  wtl + OO,  1024, 1024);
    tsplit_kernel<<<dim3(4096/32, 1024/32), tb>>>(W1, wth + O1,  wtl + O1,  1024, 4096);
    tsplit_kernel<<<dim3(1024/32, 4096/32), tb>>>(W2, wth + O2,  wtl + O2,  4096, 1024);

    split_kernel<true ><<<4096, 256>>>(src, pos,     qkh, qkl);
    split_kernel<false><<<4096, 256>>>(src, nullptr, sh,  sl);

    const dim3 gP(8, 32), gF1(32, 32);
    // projections -> bf16 hi/lo q,k,v
    gemm_tc<false,false,true ><<<gP, 256, GEMM_SMEM>>>(qkh, qkl, wth + OQ,  wtl + OQ,  bq, nullptr, nullptr, qbh, qbl, 4096, 1024, 1024);
    gemm_tc<false,false,true ><<<gP, 256, GEMM_SMEM>>>(qkh, qkl, wth + OK_, wtl + OK_, bk, nullptr, nullptr, kbh, kbl, 4096, 1024, 1024);
    gemm_tc<false,false,true ><<<gP, 256, GEMM_SMEM>>>(sh,  sl,  wth + OV,  wtl + OV,  bv, nullptr, nullptr, vbh, vbl, 4096, 1024, 1024);

    attn_mma<<<dim3(16, 32), 256, AT_SMEM>>>(qbh, qbl, kbh, kbl, vbh, vbl, corr, cth, ctl);

    gemm_tc<false,true ,false><<<gP, 256, GEMM_SMEM>>>(cth, ctl, wth + OO, wtl + OO, bo, src, y, nullptr, nullptr, 4096, 1024, 1024);
    ln_kernel<true ><<<4096, 256>>>(y, g1, be1, x, xh, xl);

    gemm_tc<true ,false,true ><<<gF1, 256, GEMM_SMEM>>>(xh,  xl,  wth + O1, wtl + O1, b1, nullptr, nullptr, ffh, ffl, 4096, 4096, 1024);
    gemm_tc<false,true ,false><<<gP,  256, GEMM_SMEM>>>(ffh, ffl, wth + O2, wtl + O2, b2, x,       y2, nullptr, nullptr, 4096, 1024, 4096);
    ln_kernel<false><<<4096, 256>>>(y2, g2, be2, out, nullptr, nullptr);
}